// round 13
// baseline (speedup 1.0000x reference)
#include <cuda_runtime.h>
#include <cuda_fp16.h>
#include <cstdint>

// ---------------- problem constants ----------------
#define BB   128
#define SS   256
#define LL   200
#define DD   768
#define PD   50
#define FF   818
#define FP   768             // gemm1 K = word_vec dims only (pos-emb folded to table)
#define RR   400
#define KR2  416             // gemm2 K padded
#define HH   150
#define NW   (BB * LL)       // 25600
#define NTAG 5
#define N4   600
#define KBI2 160             // affine/tri K padded (151 -> 160)
#define KTRI 800
#define NVOC 60
#define OUT_AP_OFF  0
#define OUT_OP_OFF  (NW * NTAG)
#define OUT_TRI_OFF (2 * NW * NTAG)

typedef __half f16;

// ---------------- scratch (__device__ globals, zero-init) ----------------
__device__ f16   g_hh[NW * FP],  g_hl[NW * FP];      // word_vecs hi/lo (A of gemm1)
__device__ f16   g_rdh[NW * KR2], g_rdl[NW * KR2];   // reduc hi/lo (A of gemm2)
__device__ float g_rep[NW * N4];
__device__ f16   g_i1h[NW * KBI2], g_i1l[NW * KBI2]; // [ap_node,1,0..] (A of affine)
__device__ f16   g_onh[NW * KBI2], g_onl[NW * KBI2]; // [op_node,0..]   (A of tri)
__device__ f16   g_afh[NW * 4 * KBI2];               // affine hi (B of tri)
__device__ f16   g_Wrh[RR * FP];                     // B of gemm1 (hi, word-vec cols)
__device__ f16   g_Wch[N4 * KR2];                    // B of gemm2
__device__ f16   g_Wbh[N4 * KBI2];                   // B of affine
__device__ float g_bcat[N4];
__device__ float g_tagtab[NVOC * RR];                // pos-emb @ Wreduc[:, :50]^T + b_reduc

__device__ __forceinline__ void hsplit(float v, f16* ph, f16* pl) {
    f16 h = __float2half(v);
    *ph = h;
    *pl = __float2half(v - __half2float(h));
}

// ---------------- PTX helpers (baseline sm_80+ features only) ----------------
__device__ __forceinline__ uint32_t sm_u32(const void* p) {
    uint32_t a;
    asm("{ .reg .u64 t; cvta.to.shared.u64 t, %1; cvt.u32.u64 %0, t; }" : "=r"(a) : "l"(p));
    return a;
}

#define CP16(dst, src) \
    asm volatile("cp.async.cg.shared.global [%0], [%1], 16;" :: "r"(dst), "l"(src) : "memory")
#define CP_COMMIT() asm volatile("cp.async.commit_group;" ::: "memory")
#define CP_WAIT0()  asm volatile("cp.async.wait_group 0;" ::: "memory")

#define LDSM4(r0, r1, r2, r3, addr) \
    asm volatile("ldmatrix.sync.aligned.m8n8.x4.shared.b16 {%0,%1,%2,%3}, [%4];" \
                 : "=r"(r0), "=r"(r1), "=r"(r2), "=r"(r3) : "r"(addr))

#define MMA16816(d, a0, a1, a2, a3, b0, b1) \
    asm volatile("mma.sync.aligned.m16n8k16.row.col.f32.f16.f16.f32 " \
                 "{%0,%1,%2,%3}, {%4,%5,%6,%7}, {%8,%9}, {%0,%1,%2,%3};" \
                 : "+f"((d)[0]), "+f"((d)[1]), "+f"((d)[2]), "+f"((d)[3]) \
                 : "r"(a0), "r"(a1), "r"(a2), "r"(a3), "r"(b0), "r"(b1))

// smem stage (bytes): rows of 32 f16 = 64B + 16B pad -> 80B stride
// A_hi 256x32, A_lo 256x32, B_hi 64x32
#define S_AH    0
#define S_AL    20480
#define S_BH    40960
#define S_STAGE 46080
#define NSTAGE  2
#define SMEM_SZ (NSTAGE * S_STAGE)    // 92160 -> 2 CTAs/SM

// ---------------- HMMA GEMM: C[M,N] = (Ahi+Alo)[M,K] * Bhi[N,K]^T ----
// 256x64 block tile, 8 warps (4Mx2N), warp tile 64x32, BK=32.
// Per warp-k16: 8 A-LDSM4 + 2 B-LDSM4 -> 64 MMAs (2 terms).
// MODE 0: +tagtab[postag] -> reduc hi/lo;  MODE 1: relu(+bias) -> g_rep + splits;
// MODE 2: -> aff hi;                        MODE 3: batched (z) -> out triplet.
template<int MODE>
__global__ __launch_bounds__(256, 2) void mma_gemm(
    const f16* __restrict__ Ahi, const f16* __restrict__ Alo, int lda, long aStride,
    const f16* __restrict__ Bhi, int ldb, long bStride,
    int M, int N, int nchunk,
    const float* __restrict__ bias, const int* __restrict__ postag,
    float* __restrict__ out)
{
    extern __shared__ char smem[];
    const uint32_t sbase = sm_u32(smem);
    const int tid = threadIdx.x;
    const int lane = tid & 31;
    const int warp = tid >> 5;
    const int warpM = warp >> 1;       // 0..3 (64 rows each)
    const int warpN = warp & 1;        // 0..1 (32 cols each)
    const int rowBase = blockIdx.y * 256;
    const int colBase = blockIdx.x * 64;
    const int z = blockIdx.z;

    const f16* ahi = Ahi + (long)z * aStride;
    const f16* alo = Alo + (long)z * aStride;
    const f16* bhi = Bhi + (long)z * bStride;

    // ldmatrix per-lane offsets (16-row granularity; same row formula as proven kernel)
    const int a_row = (lane & 7) + ((lane >> 3) & 1) * 8;
    const int a_kh  = lane >> 4;
    const uint32_t aoff = (uint32_t)((warpM * 64 + a_row) * 80 + a_kh * 16);
    const int b_n  = (lane & 7) + (lane >> 4) * 8;
    const int b_kh = (lane >> 3) & 1;
    const uint32_t boff = (uint32_t)((warpN * 32 + b_n) * 80 + b_kh * 16);

    float acc[4][4][4];
    #pragma unroll
    for (int m = 0; m < 4; m++)
        #pragma unroll
        for (int t = 0; t < 4; t++)
            #pragma unroll
            for (int r = 0; r < 4; r++) acc[m][t][r] = 0.f;

    // A loader: thread t owns A row t (4 x 16B hi + 4 x 16B lo). B: row tid&63, chunk tid>>6.
    const long garow = rowBase + tid > M - 1 ? (long)(M - 1) : (long)(rowBase + tid);
    const long gbrow = colBase + (tid & 63) > N - 1 ? (long)(N - 1) : (long)(colBase + (tid & 63));
    const int bq = tid >> 6;           // 0..3

    auto issue = [&](int c) {
        const uint32_t bufb = sbase + (c & 1) * S_STAGE;
        const int kof = c * 32;
        const uint32_t da = bufb + tid * 80;
        const f16* sa_h = ahi + garow * (long)lda + kof;
        const f16* sa_l = alo + garow * (long)lda + kof;
        #pragma unroll
        for (int q = 0; q < 4; q++) {
            CP16(da + S_AH + q * 16, sa_h + q * 8);
            CP16(da + S_AL + q * 16, sa_l + q * 8);
        }
        CP16(bufb + S_BH + (tid & 63) * 80 + bq * 16,
             bhi + gbrow * (long)ldb + kof + bq * 8);
        CP_COMMIT();
    };

    issue(0);
    for (int c = 0; c < nchunk; c++) {
        CP_WAIT0();
        __syncthreads();
        if (c + 1 < nchunk) issue(c + 1);

        const uint32_t bb = sbase + (c & 1) * S_STAGE;
        #pragma unroll
        for (int k16 = 0; k16 < 2; k16++) {
            const uint32_t ka = bb + k16 * 32 + aoff;
            const uint32_t kb = bb + k16 * 32 + boff;
            uint32_t bh[8];
            LDSM4(bh[0], bh[1], bh[2], bh[3], kb + S_BH);
            LDSM4(bh[4], bh[5], bh[6], bh[7], kb + S_BH + 16 * 80);
            uint32_t a[16];
            #pragma unroll
            for (int m = 0; m < 4; m++)
                LDSM4(a[m*4], a[m*4+1], a[m*4+2], a[m*4+3],
                      ka + S_AH + m * 16 * 80);
            #pragma unroll
            for (int m = 0; m < 4; m++)
                #pragma unroll
                for (int t8 = 0; t8 < 4; t8++) {
                    int g = t8 >> 1, s = t8 & 1;
                    MMA16816(acc[m][t8], a[m*4], a[m*4+1], a[m*4+2], a[m*4+3],
                             bh[g*4 + s*2], bh[g*4 + s*2 + 1]);
                }
            #pragma unroll
            for (int m = 0; m < 4; m++)
                LDSM4(a[m*4], a[m*4+1], a[m*4+2], a[m*4+3],
                      ka + S_AL + m * 16 * 80);
            #pragma unroll
            for (int m = 0; m < 4; m++)
                #pragma unroll
                for (int t8 = 0; t8 < 4; t8++) {
                    int g = t8 >> 1, s = t8 & 1;
                    MMA16816(acc[m][t8], a[m*4], a[m*4+1], a[m*4+2], a[m*4+3],
                             bh[g*4 + s*2], bh[g*4 + s*2 + 1]);
                }
        }
    }

    // ---- epilogue ----
    const int lr = lane >> 2;
    const int lc = (lane & 3) * 2;
    #pragma unroll
    for (int m = 0; m < 4; m++) {
        #pragma unroll
        for (int t8 = 0; t8 < 4; t8++) {
            #pragma unroll
            for (int ri = 0; ri < 4; ri++) {
                int gm = rowBase + warpM * 64 + m * 16 + lr + ((ri & 2) ? 8 : 0);
                int gn = colBase + warpN * 32 + t8 * 8 + lc + (ri & 1);
                if (gm >= M || gn >= N) continue;
                float v = acc[m][t8][ri];
                if (MODE == 0) {
                    v += g_tagtab[(long)postag[gm] * RR + gn];
                    hsplit(v, &g_rdh[(long)gm * KR2 + gn], &g_rdl[(long)gm * KR2 + gn]);
                } else if (MODE == 1) {
                    v = fmaxf(v + bias[gn], 0.f);
                    g_rep[(long)gm * N4 + gn] = v;
                    if (gn >= 300 && gn < 450)
                        hsplit(v, &g_i1h[(long)gm * KBI2 + gn - 300],
                                  &g_i1l[(long)gm * KBI2 + gn - 300]);
                    else if (gn >= 450)
                        hsplit(v, &g_onh[(long)gm * KBI2 + gn - 450],
                                  &g_onl[(long)gm * KBI2 + gn - 450]);
                } else if (MODE == 2) {
                    int p = gn / HH, h = gn - p * HH;
                    g_afh[((long)gm * 4 + p) * KBI2 + h] = __float2half(v);
                } else {
                    out[(long)OUT_TRI_OFF + ((long)z * LL + gm) * KTRI + gn] = v;
                }
            }
        }
    }
}

// ---------------- postag table: T[t][n] = b_reduc[n] + embed[t] . W_reduc[n][:50] ----
__global__ void tagtab_kernel(const float* __restrict__ embed,
                              const float* __restrict__ W_reduc,
                              const float* __restrict__ b_reduc) {
    int idx = blockIdx.x * blockDim.x + threadIdx.x;
    if (idx >= NVOC * RR) return;
    int t = idx / RR, n = idx - t * RR;
    float s = b_reduc[n];
    #pragma unroll 10
    for (int j = 0; j < PD; j++) s += embed[t * PD + j] * W_reduc[n * FF + j];
    g_tagtab[idx] = s;
}

// ---------------- pack weights into f16 hi ----------------
__global__ void pack_kernel(const float* __restrict__ W_ap, const float* __restrict__ b_ap,
                            const float* __restrict__ W_op, const float* __restrict__ b_op,
                            const float* __restrict__ W_ap2, const float* __restrict__ b_ap2,
                            const float* __restrict__ W_op2, const float* __restrict__ b_op2,
                            const float* __restrict__ W_reduc, const float* __restrict__ W_bi) {
    int idx = blockIdx.x * blockDim.x + threadIdx.x;
    const int T0 = RR * FP;
    const int T1 = T0 + N4 * KR2;
    const int T2 = T1 + N4 * KBI2;
    const int T3 = T2 + N4;
    if (idx < T0) {
        int n = idx / FP, k = idx - n * FP;
        g_Wrh[idx] = __float2half(W_reduc[n * FF + PD + k]);   // word-vec columns
    } else if (idx < T1) {
        int i = idx - T0;
        int n = i / KR2, k = i - n * KR2;
        float v = 0.f;
        if (k < RR) {
            const float* src; int nn = n;
            if (n < HH)          { src = W_ap;  }
            else if (n < 2 * HH) { src = W_op;  nn = n - HH; }
            else if (n < 3 * HH) { src = W_ap2; nn = n - 2 * HH; }
            else                 { src = W_op2; nn = n - 3 * HH; }
            v = src[nn * RR + k];
        }
        g_Wch[i] = __float2half(v);
    } else if (idx < T2) {
        int i = idx - T1;
        int n = i / KBI2, k = i - n * KBI2;
        float v = (k < HH + 1) ? W_bi[n * (HH + 1) + k] : 0.f;
        g_Wbh[i] = __float2half(v);
    } else if (idx < T3) {
        int n = idx - T2;
        const float* src; int nn = n;
        if (n < HH)          { src = b_ap;  }
        else if (n < 2 * HH) { src = b_op;  nn = n - HH; }
        else if (n < 3 * HH) { src = b_ap2; nn = n - 2 * HH; }
        else                 { src = b_op2; nn = n - 3 * HH; }
        g_bcat[n] = src[nn];
    }
}

// set bias-1 column of in1
__global__ void init_kernel() {
    int w = blockIdx.x * blockDim.x + threadIdx.x;
    if (w < NW) {
        g_i1h[(long)w * KBI2 + HH] = __float2half(1.0f);
        g_i1l[(long)w * KBI2 + HH] = __float2half(0.0f);
    }
}

// ---------------- pool subwords (word_vecs only) -> f16 hi/lo ----------------
__global__ void pool_kernel(const float* __restrict__ bert,
                            const int* __restrict__ positions) {
    int idx = blockIdx.x * blockDim.x + threadIdx.x;
    if (idx >= NW * FP) return;
    int w = idx / FP;
    int d = idx - w * FP;
    int s0 = positions[2 * w];
    int s1 = positions[2 * w + 1];
    int b  = w / LL;
    const float* base = bert + ((long)b * SS) * DD + d;
    float s = 0.f;
    for (int t = s0; t <= s1; t++) s += base[(long)t * DD];
    float v = s / (float)(s1 - s0 + 1);
    hsplit(v, &g_hh[idx], &g_hl[idx]);
}

// ---------------- tag heads (tiny) ----------------
__global__ void tag_kernel(const float* __restrict__ W_aptag, const float* __restrict__ b_aptag,
                           const float* __restrict__ W_optag, const float* __restrict__ b_optag,
                           float* __restrict__ out) {
    int idx = blockIdx.x * blockDim.x + threadIdx.x;
    if (idx >= NW * 10) return;
    int w = idx / 10, t = idx - w * 10;
    const float* rep;
    const float* wv;
    float acc;
    int off;
    if (t < NTAG) {
        rep = g_rep + (long)w * N4;
        wv  = W_aptag + t * HH;
        acc = b_aptag[t];
        off = OUT_AP_OFF + w * NTAG + t;
    } else {
        int tt = t - NTAG;
        rep = g_rep + (long)w * N4 + HH;
        wv  = W_optag + tt * HH;
        acc = b_optag[tt];
        off = OUT_OP_OFF + w * NTAG + tt;
    }
    #pragma unroll 5
    for (int k = 0; k < HH; k++) acc += rep[k] * wv[k];
    out[off] = acc;
}

// ---------------- launch ----------------
extern "C" void kernel_launch(void* const* d_in, const int* in_sizes, int n_in,
                              void* d_out, int out_size) {
    const float* bert      = (const float*)d_in[0];
    const int*   positions = (const int*)  d_in[1];
    const int*   postag    = (const int*)  d_in[2];
    const float* embed     = (const float*)d_in[3];
    const float* W_reduc   = (const float*)d_in[4];
    const float* b_reduc   = (const float*)d_in[5];
    const float* W_ap      = (const float*)d_in[6];
    const float* b_ap      = (const float*)d_in[7];
    const float* W_op      = (const float*)d_in[8];
    const float* b_op      = (const float*)d_in[9];
    const float* W_ap2     = (const float*)d_in[10];
    const float* b_ap2     = (const float*)d_in[11];
    const float* W_op2     = (const float*)d_in[12];
    const float* b_op2     = (const float*)d_in[13];
    const float* W_aptag   = (const float*)d_in[14];
    const float* b_aptag   = (const float*)d_in[15];
    const float* W_optag   = (const float*)d_in[16];
    const float* b_optag   = (const float*)d_in[17];
    const float* W_bi      = (const float*)d_in[18];
    float* out = (float*)d_out;

    void* p;
    cudaGetSymbolAddress(&p, g_hh);   f16* phh  = (f16*)p;
    cudaGetSymbolAddress(&p, g_hl);   f16* phl  = (f16*)p;
    cudaGetSymbolAddress(&p, g_rdh);  f16* prdh = (f16*)p;
    cudaGetSymbolAddress(&p, g_rdl);  f16* prdl = (f16*)p;
    cudaGetSymbolAddress(&p, g_i1h);  f16* pi1h = (f16*)p;
    cudaGetSymbolAddress(&p, g_i1l);  f16* pi1l = (f16*)p;
    cudaGetSymbolAddress(&p, g_onh);  f16* ponh = (f16*)p;
    cudaGetSymbolAddress(&p, g_onl);  f16* ponl = (f16*)p;
    cudaGetSymbolAddress(&p, g_afh);  f16* pafh = (f16*)p;
    cudaGetSymbolAddress(&p, g_Wrh);  f16* pWrh = (f16*)p;
    cudaGetSymbolAddress(&p, g_Wch);  f16* pWch = (f16*)p;
    cudaGetSymbolAddress(&p, g_Wbh);  f16* pWbh = (f16*)p;
    cudaGetSymbolAddress(&p, g_bcat); float* pbcat = (float*)p;

    cudaFuncSetAttribute(mma_gemm<0>, cudaFuncAttributeMaxDynamicSharedMemorySize, SMEM_SZ);
    cudaFuncSetAttribute(mma_gemm<1>, cudaFuncAttributeMaxDynamicSharedMemorySize, SMEM_SZ);
    cudaFuncSetAttribute(mma_gemm<2>, cudaFuncAttributeMaxDynamicSharedMemorySize, SMEM_SZ);
    cudaFuncSetAttribute(mma_gemm<3>, cudaFuncAttributeMaxDynamicSharedMemorySize, SMEM_SZ);

    // 1) pack weights + tag table + bias column
    {
        int tot = RR * FP + N4 * KR2 + N4 * KBI2 + N4;
        pack_kernel<<<(tot + 255) / 256, 256>>>(W_ap, b_ap, W_op, b_op, W_ap2, b_ap2,
                                                W_op2, b_op2, W_reduc, W_bi);
        tagtab_kernel<<<(NVOC * RR + 255) / 256, 256>>>(embed, W_reduc, b_reduc);
        init_kernel<<<(NW + 255) / 256, 256>>>();
    }
    // 2) pool word_vecs -> f16 hi/lo
    {
        int tot = NW * FP;
        pool_kernel<<<(tot + 255) / 256, 256>>>(bert, positions);
    }
    // 3) gemm1: reduc = wv @ Wr^T + tagtab[postag]   M=25600, N=400, K=768 (24 chunks)
    {
        dim3 grid(7, NW / 256, 1);
        mma_gemm<0><<<grid, 256, SMEM_SZ>>>(phh, phl, FP, 0, pWrh, FP, 0,
                                            NW, RR, FP / 32, nullptr, postag, nullptr);
    }
    // 4) gemm2: rep = relu(reduc @ Wcat^T + bcat)  M=25600, N=600, K=416 (13 chunks)
    {
        dim3 grid(10, NW / 256, 1);
        mma_gemm<1><<<grid, 256, SMEM_SZ>>>(prdh, prdl, KR2, 0, pWch, KR2, 0,
                                            NW, N4, KR2 / 32, pbcat, nullptr, nullptr);
    }
    // 5) tag heads
    {
        int tot = NW * 10;
        tag_kernel<<<(tot + 255) / 256, 256>>>(W_aptag, b_aptag, W_optag, b_optag, out);
    }
    // 6) affine = in1 @ Wbi^T   M=25600, N=600, K=160 (5 chunks)
    {
        dim3 grid(10, NW / 256, 1);
        mma_gemm<2><<<grid, 256, SMEM_SZ>>>(pi1h, pi1l, KBI2, 0, pWbh, KBI2, 0,
                                            NW, N4, KBI2 / 32, nullptr, nullptr, nullptr);
    }
    // 7) tri: batched  M=200 (one 256-tile), N=800, K=160 per batch (5 chunks)
    {
        dim3 grid(13, 1, BB);
        mma_gemm<3><<<grid, 256, SMEM_SZ>>>(ponh, ponl, KBI2, (long)LL * KBI2,
                                            pafh, KBI2, (long)LL * 4 * KBI2,
                                            LL, KTRI, KBI2 / 32, nullptr, nullptr, out);
    }
}

// round 14
// speedup vs baseline: 1.5030x; 1.5030x over previous
#include <cuda_runtime.h>
#include <cuda_fp16.h>
#include <cstdint>

// ---------------- problem constants ----------------
#define BB   128
#define SS   256
#define LL   200
#define DD   768
#define PD   50
#define FF   818
#define FP   768             // gemm1 K = word_vec dims only (pos-emb folded into table)
#define RR   400
#define KR2  416             // gemm2 K padded
#define HH   150
#define NW   (BB * LL)       // 25600
#define NTAG 5
#define N4   600
#define KBI2 160             // affine/tri K padded (151 -> 160)
#define KTRI 800
#define NVOC 60
#define OUT_AP_OFF  0
#define OUT_OP_OFF  (NW * NTAG)
#define OUT_TRI_OFF (2 * NW * NTAG)

typedef __half f16;

// ---------------- scratch (__device__ globals, zero-init) ----------------
__device__ f16   g_hh[NW * FP],  g_hl[NW * FP];      // word_vecs hi/lo (A of gemm1)
__device__ f16   g_rdh[NW * KR2], g_rdl[NW * KR2];   // reduc hi/lo (A of gemm2)
__device__ float g_rep[NW * N4];
__device__ f16   g_i1h[NW * KBI2], g_i1l[NW * KBI2]; // [ap_node,1,0..] (A of affine)
__device__ f16   g_onh[NW * KBI2], g_onl[NW * KBI2]; // [op_node,0..]   (A of tri)
__device__ f16   g_afh[NW * 4 * KBI2];               // affine hi (B of tri)
__device__ f16   g_Wrh[RR * FP];                     // B of gemm1 (hi, word-vec cols)
__device__ f16   g_Wch[N4 * KR2];                    // B of gemm2
__device__ f16   g_Wbh[N4 * KBI2];                   // B of affine
__device__ float g_bcat[N4];
__device__ float g_tagtab[NVOC * RR];                // embed @ Wreduc[:, :50]^T + b_reduc

__device__ __forceinline__ void hsplit(float v, f16* ph, f16* pl) {
    f16 h = __float2half(v);
    *ph = h;
    *pl = __float2half(v - __half2float(h));
}

// ---------------- PTX helpers (baseline sm_80+ features only) ----------------
__device__ __forceinline__ uint32_t sm_u32(const void* p) {
    uint32_t a;
    asm("{ .reg .u64 t; cvta.to.shared.u64 t, %1; cvt.u32.u64 %0, t; }" : "=r"(a) : "l"(p));
    return a;
}

#define CP16(dst, src) \
    asm volatile("cp.async.cg.shared.global [%0], [%1], 16;" :: "r"(dst), "l"(src) : "memory")
#define CP_COMMIT() asm volatile("cp.async.commit_group;" ::: "memory")
#define CP_WAIT0()  asm volatile("cp.async.wait_group 0;" ::: "memory")

#define LDSM4(r0, r1, r2, r3, addr) \
    asm volatile("ldmatrix.sync.aligned.m8n8.x4.shared.b16 {%0,%1,%2,%3}, [%4];" \
                 : "=r"(r0), "=r"(r1), "=r"(r2), "=r"(r3) : "r"(addr))

#define MMA16816(d, a0, a1, a2, a3, b0, b1) \
    asm volatile("mma.sync.aligned.m16n8k16.row.col.f32.f16.f16.f32 " \
                 "{%0,%1,%2,%3}, {%4,%5,%6,%7}, {%8,%9}, {%0,%1,%2,%3};" \
                 : "+f"((d)[0]), "+f"((d)[1]), "+f"((d)[2]), "+f"((d)[3]) \
                 : "r"(a0), "r"(a1), "r"(a2), "r"(a3), "r"(b0), "r"(b1))

// smem stage layout (bytes): rows of 32 f16 = 64B + 16B pad -> 80B row stride
// A_hi 128x32, A_lo 128x32, B_hi 64x32
#define S_AH    0
#define S_AL    10240
#define S_BH    20480
#define S_STAGE 25600
#define NSTAGE  2
#define SMEM_SZ (NSTAGE * S_STAGE)    // 51200 -> 3 CTAs/SM

// ---------------- HMMA GEMM: C[M,N] = (Ahi+Alo)[M,K] * Bhi[N,K]^T ----
// (proven R11 config: 128x64 block tile, 8 warps 4Mx2N, warp tile 32x32, BK=32,
//  2-stage cp.async pipeline, one __syncthreads per chunk, 3 CTAs/SM.)
// MODE 0: +tagtab[postag] -> reduc hi/lo;  MODE 1: relu(+bias) -> g_rep + splits;
// MODE 2: -> aff hi;                        MODE 3: batched (z) -> out triplet.
template<int MODE>
__global__ __launch_bounds__(256, 3) void mma_gemm(
    const f16* __restrict__ Ahi, const f16* __restrict__ Alo, int lda, long aStride,
    const f16* __restrict__ Bhi, int ldb, long bStride,
    int M, int N, int nchunk,
    const float* __restrict__ bias, const int* __restrict__ postag,
    float* __restrict__ out)
{
    extern __shared__ char smem[];
    const uint32_t sbase = sm_u32(smem);
    const int tid = threadIdx.x;
    const int lane = tid & 31;
    const int warp = tid >> 5;
    const int warpM = warp >> 1;       // 0..3
    const int warpN = warp & 1;        // 0..1
    const int rowBase = blockIdx.y * 128;
    const int colBase = blockIdx.x * 64;
    const int z = blockIdx.z;

    const f16* ahi = Ahi + (long)z * aStride;
    const f16* alo = Alo + (long)z * aStride;
    const f16* bhi = Bhi + (long)z * bStride;

    // loader mapping
    const int lrow = tid >> 2;         // 0..63
    const int lc8  = tid & 3;          // 16B chunk within 64B row

    // ldmatrix per-lane offsets
    const int a_row = (lane & 7) + ((lane >> 3) & 1) * 8;
    const int a_kh  = lane >> 4;
    const uint32_t aoff = (uint32_t)((warpM * 32 + a_row) * 80 + a_kh * 16);
    const int b_n  = (lane & 7) + (lane >> 4) * 8;
    const int b_kh = (lane >> 3) & 1;
    const uint32_t boff = (uint32_t)((warpN * 32 + b_n) * 80 + b_kh * 16);

    float acc[2][4][4];
    #pragma unroll
    for (int m = 0; m < 2; m++)
        #pragma unroll
        for (int t = 0; t < 4; t++)
            #pragma unroll
            for (int r = 0; r < 4; r++) acc[m][t][r] = 0.f;

    // ---- async copy of one K-chunk (32 f16) into stage buffer ----
    auto issue = [&](int c) {
        const uint32_t bufb = sbase + (c & 1) * S_STAGE;
        const int kof = c * 32 + lc8 * 8;
        #pragma unroll
        for (int t = 0; t < 2; t++) {
            int row = lrow + t * 64;
            long gr = rowBase + row; if (gr > M - 1) gr = M - 1;
            uint32_t d = bufb + row * 80 + lc8 * 16;
            CP16(d + S_AH, ahi + gr * (long)lda + kof);
            CP16(d + S_AL, alo + gr * (long)lda + kof);
        }
        {
            long gn = colBase + lrow; if (gn > N - 1) gn = N - 1;
            uint32_t d = bufb + S_BH + lrow * 80 + lc8 * 16;
            CP16(d, bhi + gn * (long)ldb + kof);
        }
        CP_COMMIT();
    };

    issue(0);
    for (int c = 0; c < nchunk; c++) {
        CP_WAIT0();                 // copy of chunk c landed
        __syncthreads();            // everyone done computing chunk c-1
        if (c + 1 < nchunk) issue(c + 1);   // overlaps compute(c)

        const uint32_t bb = sbase + (c & 1) * S_STAGE;
        #pragma unroll
        for (int k16 = 0; k16 < 2; k16++) {
            const uint32_t ka = bb + k16 * 32 + aoff;
            const uint32_t kb = bb + k16 * 32 + boff;
            uint32_t ah[8], al[8], bh[8];
            LDSM4(ah[0], ah[1], ah[2], ah[3], ka + S_AH);
            LDSM4(ah[4], ah[5], ah[6], ah[7], ka + S_AH + 16 * 80);
            LDSM4(al[0], al[1], al[2], al[3], ka + S_AL);
            LDSM4(al[4], al[5], al[6], al[7], ka + S_AL + 16 * 80);
            LDSM4(bh[0], bh[1], bh[2], bh[3], kb + S_BH);
            LDSM4(bh[4], bh[5], bh[6], bh[7], kb + S_BH + 16 * 80);
            #pragma unroll
            for (int m = 0; m < 2; m++) {
                #pragma unroll
                for (int t8 = 0; t8 < 4; t8++) {
                    int g = t8 >> 1, s = t8 & 1;
                    uint32_t b0 = bh[g * 4 + s * 2], b1 = bh[g * 4 + s * 2 + 1];
                    MMA16816(acc[m][t8], ah[m*4], ah[m*4+1], ah[m*4+2], ah[m*4+3], b0, b1);
                    MMA16816(acc[m][t8], al[m*4], al[m*4+1], al[m*4+2], al[m*4+3], b0, b1);
                }
            }
        }
    }

    // ---- epilogue ----
    const int lr = lane >> 2;
    const int lc = (lane & 3) * 2;
    #pragma unroll
    for (int m = 0; m < 2; m++) {
        #pragma unroll
        for (int t8 = 0; t8 < 4; t8++) {
            #pragma unroll
            for (int ri = 0; ri < 4; ri++) {
                int gm = rowBase + warpM * 32 + m * 16 + lr + ((ri & 2) ? 8 : 0);
                int gn = colBase + warpN * 32 + t8 * 8 + lc + (ri & 1);
                if (gm >= M || gn >= N) continue;
                float v = acc[m][t8][ri];
                if (MODE == 0) {
                    v += g_tagtab[(long)postag[gm] * RR + gn];
                    hsplit(v, &g_rdh[(long)gm * KR2 + gn], &g_rdl[(long)gm * KR2 + gn]);
                } else if (MODE == 1) {
                    v = fmaxf(v + bias[gn], 0.f);
                    g_rep[(long)gm * N4 + gn] = v;
                    if (gn >= 300 && gn < 450)
                        hsplit(v, &g_i1h[(long)gm * KBI2 + gn - 300],
                                  &g_i1l[(long)gm * KBI2 + gn - 300]);
                    else if (gn >= 450)
                        hsplit(v, &g_onh[(long)gm * KBI2 + gn - 450],
                                  &g_onl[(long)gm * KBI2 + gn - 450]);
                } else if (MODE == 2) {
                    int p = gn / HH, h = gn - p * HH;
                    g_afh[((long)gm * 4 + p) * KBI2 + h] = __float2half(v);
                } else {
                    out[(long)OUT_TRI_OFF + ((long)z * LL + gm) * KTRI + gn] = v;
                }
            }
        }
    }
}

// ---------------- postag table: T[t][n] = b_reduc[n] + embed[t] . W_reduc[n][:50] ----
__global__ void tagtab_kernel(const float* __restrict__ embed,
                              const float* __restrict__ W_reduc,
                              const float* __restrict__ b_reduc) {
    int idx = blockIdx.x * blockDim.x + threadIdx.x;
    if (idx >= NVOC * RR) return;
    int t = idx / RR, n = idx - t * RR;
    float s = b_reduc[n];
    #pragma unroll 10
    for (int j = 0; j < PD; j++) s += embed[t * PD + j] * W_reduc[n * FF + j];
    g_tagtab[idx] = s;
}

// ---------------- pack weights into f16 hi ----------------
__global__ void pack_kernel(const float* __restrict__ W_ap, const float* __restrict__ b_ap,
                            const float* __restrict__ W_op, const float* __restrict__ b_op,
                            const float* __restrict__ W_ap2, const float* __restrict__ b_ap2,
                            const float* __restrict__ W_op2, const float* __restrict__ b_op2,
                            const float* __restrict__ W_reduc, const float* __restrict__ W_bi) {
    int idx = blockIdx.x * blockDim.x + threadIdx.x;
    const int T0 = RR * FP;
    const int T1 = T0 + N4 * KR2;
    const int T2 = T1 + N4 * KBI2;
    const int T3 = T2 + N4;
    if (idx < T0) {
        int n = idx / FP, k = idx - n * FP;
        g_Wrh[idx] = __float2half(W_reduc[n * FF + PD + k]);   // word-vec columns only
    } else if (idx < T1) {
        int i = idx - T0;
        int n = i / KR2, k = i - n * KR2;
        float v = 0.f;
        if (k < RR) {
            const float* src; int nn = n;
            if (n < HH)          { src = W_ap;  }
            else if (n < 2 * HH) { src = W_op;  nn = n - HH; }
            else if (n < 3 * HH) { src = W_ap2; nn = n - 2 * HH; }
            else                 { src = W_op2; nn = n - 3 * HH; }
            v = src[nn * RR + k];
        }
        g_Wch[i] = __float2half(v);
    } else if (idx < T2) {
        int i = idx - T1;
        int n = i / KBI2, k = i - n * KBI2;
        float v = (k < HH + 1) ? W_bi[n * (HH + 1) + k] : 0.f;
        g_Wbh[i] = __float2half(v);
    } else if (idx < T3) {
        int n = idx - T2;
        const float* src; int nn = n;
        if (n < HH)          { src = b_ap;  }
        else if (n < 2 * HH) { src = b_op;  nn = n - HH; }
        else if (n < 3 * HH) { src = b_ap2; nn = n - 2 * HH; }
        else                 { src = b_op2; nn = n - 3 * HH; }
        g_bcat[n] = src[nn];
    }
}

// set bias-1 column of in1
__global__ void init_kernel() {
    int w = blockIdx.x * blockDim.x + threadIdx.x;
    if (w < NW) {
        g_i1h[(long)w * KBI2 + HH] = __float2half(1.0f);
        g_i1l[(long)w * KBI2 + HH] = __float2half(0.0f);
    }
}

// ---------------- pool subwords (word_vecs only), 4 dims/thread ----------------
__global__ void pool_kernel(const float* __restrict__ bert,
                            const int* __restrict__ positions) {
    int idx = blockIdx.x * blockDim.x + threadIdx.x;
    if (idx >= NW * (FP / 4)) return;
    int w  = idx / (FP / 4);
    int d4 = (idx - w * (FP / 4)) * 4;
    int s0 = positions[2 * w];
    int s1 = positions[2 * w + 1];
    int b  = w / LL;
    const float* base = bert + ((long)b * SS) * DD + d4;
    float4 s = make_float4(0.f, 0.f, 0.f, 0.f);
    for (int t = s0; t <= s1; t++) {
        float4 v = *(const float4*)(base + (long)t * DD);
        s.x += v.x; s.y += v.y; s.z += v.z; s.w += v.w;
    }
    float inv = 1.0f / (float)(s1 - s0 + 1);
    long o = (long)w * FP + d4;
    f16 h0, l0, h1, l1, h2, l2, h3, l3;
    hsplit(s.x * inv, &h0, &l0);
    hsplit(s.y * inv, &h1, &l1);
    hsplit(s.z * inv, &h2, &l2);
    hsplit(s.w * inv, &h3, &l3);
    __half2* ph = (__half2*)(g_hh + o);
    __half2* pl = (__half2*)(g_hl + o);
    ph[0] = __halves2half2(h0, h1);
    ph[1] = __halves2half2(h2, h3);
    pl[0] = __halves2half2(l0, l1);
    pl[1] = __halves2half2(l2, l3);
}

// ---------------- tag heads (tiny) ----------------
__global__ void tag_kernel(const float* __restrict__ W_aptag, const float* __restrict__ b_aptag,
                           const float* __restrict__ W_optag, const float* __restrict__ b_optag,
                           float* __restrict__ out) {
    int idx = blockIdx.x * blockDim.x + threadIdx.x;
    if (idx >= NW * 10) return;
    int w = idx / 10, t = idx - w * 10;
    const float* rep;
    const float* wv;
    float acc;
    int off;
    if (t < NTAG) {
        rep = g_rep + (long)w * N4;
        wv  = W_aptag + t * HH;
        acc = b_aptag[t];
        off = OUT_AP_OFF + w * NTAG + t;
    } else {
        int tt = t - NTAG;
        rep = g_rep + (long)w * N4 + HH;
        wv  = W_optag + tt * HH;
        acc = b_optag[tt];
        off = OUT_OP_OFF + w * NTAG + tt;
    }
    #pragma unroll 5
    for (int k = 0; k < HH; k++) acc += rep[k] * wv[k];
    out[off] = acc;
}

// ---------------- launch ----------------
extern "C" void kernel_launch(void* const* d_in, const int* in_sizes, int n_in,
                              void* d_out, int out_size) {
    const float* bert      = (const float*)d_in[0];
    const int*   positions = (const int*)  d_in[1];
    const int*   postag    = (const int*)  d_in[2];
    const float* embed     = (const float*)d_in[3];
    const float* W_reduc   = (const float*)d_in[4];
    const float* b_reduc   = (const float*)d_in[5];
    const float* W_ap      = (const float*)d_in[6];
    const float* b_ap      = (const float*)d_in[7];
    const float* W_op      = (const float*)d_in[8];
    const float* b_op      = (const float*)d_in[9];
    const float* W_ap2     = (const float*)d_in[10];
    const float* b_ap2     = (const float*)d_in[11];
    const float* W_op2     = (const float*)d_in[12];
    const float* b_op2     = (const float*)d_in[13];
    const float* W_aptag   = (const float*)d_in[14];
    const float* b_aptag   = (const float*)d_in[15];
    const float* W_optag   = (const float*)d_in[16];
    const float* b_optag   = (const float*)d_in[17];
    const float* W_bi      = (const float*)d_in[18];
    float* out = (float*)d_out;

    void* p;
    cudaGetSymbolAddress(&p, g_hh);   f16* phh  = (f16*)p;
    cudaGetSymbolAddress(&p, g_hl);   f16* phl  = (f16*)p;
    cudaGetSymbolAddress(&p, g_rdh);  f16* prdh = (f16*)p;
    cudaGetSymbolAddress(&p, g_rdl);  f16* prdl = (f16*)p;
    cudaGetSymbolAddress(&p, g_i1h);  f16* pi1h = (f16*)p;
    cudaGetSymbolAddress(&p, g_i1l);  f16* pi1l = (f16*)p;
    cudaGetSymbolAddress(&p, g_onh);  f16* ponh = (f16*)p;
    cudaGetSymbolAddress(&p, g_onl);  f16* ponl = (f16*)p;
    cudaGetSymbolAddress(&p, g_afh);  f16* pafh = (f16*)p;
    cudaGetSymbolAddress(&p, g_Wrh);  f16* pWrh = (f16*)p;
    cudaGetSymbolAddress(&p, g_Wch);  f16* pWch = (f16*)p;
    cudaGetSymbolAddress(&p, g_Wbh);  f16* pWbh = (f16*)p;
    cudaGetSymbolAddress(&p, g_bcat); float* pbcat = (float*)p;

    cudaFuncSetAttribute(mma_gemm<0>, cudaFuncAttributeMaxDynamicSharedMemorySize, SMEM_SZ);
    cudaFuncSetAttribute(mma_gemm<1>, cudaFuncAttributeMaxDynamicSharedMemorySize, SMEM_SZ);
    cudaFuncSetAttribute(mma_gemm<2>, cudaFuncAttributeMaxDynamicSharedMemorySize, SMEM_SZ);
    cudaFuncSetAttribute(mma_gemm<3>, cudaFuncAttributeMaxDynamicSharedMemorySize, SMEM_SZ);

    // 1) pack weights + tag table + bias column
    {
        int tot = RR * FP + N4 * KR2 + N4 * KBI2 + N4;
        pack_kernel<<<(tot + 255) / 256, 256>>>(W_ap, b_ap, W_op, b_op, W_ap2, b_ap2,
                                                W_op2, b_op2, W_reduc, W_bi);
        tagtab_kernel<<<(NVOC * RR + 255) / 256, 256>>>(embed, W_reduc, b_reduc);
        init_kernel<<<(NW + 255) / 256, 256>>>();
    }
    // 2) pool word_vecs -> f16 hi/lo (vectorized)
    {
        int tot = NW * (FP / 4);
        pool_kernel<<<(tot + 255) / 256, 256>>>(bert, positions);
    }
    // 3) gemm1: reduc = wv @ Wr^T + tagtab[postag]   M=25600, N=400, K=768 (24 chunks)
    {
        dim3 grid(7, NW / 128, 1);
        mma_gemm<0><<<grid, 256, SMEM_SZ>>>(phh, phl, FP, 0, pWrh, FP, 0,
                                            NW, RR, FP / 32, nullptr, postag, nullptr);
    }
    // 4) gemm2: rep = relu(reduc @ Wcat^T + bcat)  M=25600, N=600, K=416 (13 chunks)
    {
        dim3 grid(10, NW / 128, 1);
        mma_gemm<1><<<grid, 256, SMEM_SZ>>>(prdh, prdl, KR2, 0, pWch, KR2, 0,
                                            NW, N4, KR2 / 32, pbcat, nullptr, nullptr);
    }
    // 5) tag heads
    {
        int tot = NW * 10;
        tag_kernel<<<(tot + 255) / 256, 256>>>(W_aptag, b_aptag, W_optag, b_optag, out);
    }
    // 6) affine = in1 @ Wbi^T   M=25600, N=600, K=160 (5 chunks)
    {
        dim3 grid(10, NW / 128, 1);
        mma_gemm<2><<<grid, 256, SMEM_SZ>>>(pi1h, pi1l, KBI2, 0, pWbh, KBI2, 0,
                                            NW, N4, KBI2 / 32, nullptr, nullptr, nullptr);
    }
    // 7) tri: batched  M=200, N=800, K=160 per batch (5 chunks)
    {
        dim3 grid(13, 2, BB);
        mma_gemm<3><<<grid, 256, SMEM_SZ>>>(ponh, ponl, KBI2, (long)LL * KBI2,
                                            pafh, KBI2, (long)LL * 4 * KBI2,
                                            LL, KTRI, KBI2 / 32, nullptr, nullptr, out);
    }
}

// round 15
// speedup vs baseline: 1.5225x; 1.0130x over previous
#include <cuda_runtime.h>
#include <cuda_fp16.h>
#include <cstdint>

// ---------------- problem constants ----------------
#define BB   128
#define SS   256
#define LL   200
#define DD   768
#define PD   50
#define FF   818
#define FP   768             // gemm1 K = word_vec dims only (pos-emb folded into table)
#define RR   400
#define KR2  416             // gemm2 K padded
#define HH   150
#define NW   (BB * LL)       // 25600
#define NTAG 5
#define N4   600
#define KBI2 160             // affine/tri K padded (151 -> 160)
#define KTRI 800
#define NVOC 60
#define OUT_AP_OFF  0
#define OUT_OP_OFF  (NW * NTAG)
#define OUT_TRI_OFF (2 * NW * NTAG)

typedef __half f16;

// ---------------- scratch (__device__ globals, zero-init) ----------------
__device__ f16   g_hh[NW * FP],  g_hl[NW * FP];      // word_vecs hi/lo (A of gemm1)
__device__ f16   g_rdh[NW * KR2], g_rdl[NW * KR2];   // reduc hi/lo (A of gemm2)
__device__ float g_rep[NW * N4];                      // only cols 0..299 written/used
__device__ f16   g_i1h[NW * KBI2], g_i1l[NW * KBI2]; // [ap_node,1,0..] (A of affine)
__device__ f16   g_onh[NW * KBI2], g_onl[NW * KBI2]; // [op_node,0..]   (A of tri)
__device__ f16   g_afh[NW * 4 * KBI2];               // affine hi (B of tri)
__device__ f16   g_Wrh[RR * FP];                     // B of gemm1 (hi, word-vec cols)
__device__ f16   g_Wch[N4 * KR2];                    // B of gemm2
__device__ f16   g_Wbh[N4 * KBI2];                   // B of affine
__device__ float g_bcat[N4];
__device__ float g_tagtab[NVOC * RR];                // embed @ Wreduc[:, :50]^T + b_reduc

__device__ __forceinline__ void hsplit(float v, f16* ph, f16* pl) {
    f16 h = __float2half(v);
    *ph = h;
    *pl = __float2half(v - __half2float(h));
}

// ---------------- PTX helpers (baseline sm_80+ features only) ----------------
__device__ __forceinline__ uint32_t sm_u32(const void* p) {
    uint32_t a;
    asm("{ .reg .u64 t; cvta.to.shared.u64 t, %1; cvt.u32.u64 %0, t; }" : "=r"(a) : "l"(p));
    return a;
}

#define CP16(dst, src) \
    asm volatile("cp.async.cg.shared.global [%0], [%1], 16;" :: "r"(dst), "l"(src) : "memory")
#define CP_COMMIT() asm volatile("cp.async.commit_group;" ::: "memory")
#define CP_WAIT1()  asm volatile("cp.async.wait_group 1;" ::: "memory")
#define CP_WAIT0()  asm volatile("cp.async.wait_group 0;" ::: "memory")

#define LDSM4(r0, r1, r2, r3, addr) \
    asm volatile("ldmatrix.sync.aligned.m8n8.x4.shared.b16 {%0,%1,%2,%3}, [%4];" \
                 : "=r"(r0), "=r"(r1), "=r"(r2), "=r"(r3) : "r"(addr))

#define MMA16816(d, a0, a1, a2, a3, b0, b1) \
    asm volatile("mma.sync.aligned.m16n8k16.row.col.f32.f16.f16.f32 " \
                 "{%0,%1,%2,%3}, {%4,%5,%6,%7}, {%8,%9}, {%0,%1,%2,%3};" \
                 : "+f"((d)[0]), "+f"((d)[1]), "+f"((d)[2]), "+f"((d)[3]) \
                 : "r"(a0), "r"(a1), "r"(a2), "r"(a3), "r"(b0), "r"(b1))

// smem stage layout (bytes): rows of 32 f16 = 64B + 16B pad -> 80B row stride
// A_hi 128x32, A_lo 128x32, B_hi 64x32
#define S_AH    0
#define S_AL    10240
#define S_BH    20480
#define S_STAGE 25600
#define NSTAGE  3
#define SMEM_SZ (NSTAGE * S_STAGE)    // 76800 -> 3 CTAs/SM (230.4 KB of 233 KB)

// ---------------- HMMA GEMM: C[M,N] = (Ahi+Alo)[M,K] * Bhi[N,K]^T ----
// 128x64 block tile, 8 warps (4Mx2N), warp tile 32x32, BK=32.
// 3-stage cp.async pipeline with wait_group 1: copy(c+2) issued at iter c,
// wait at iter c only requires group c complete (group c+1 may be in flight).
// MODE 0: +tagtab[postag] -> reduc hi/lo;  MODE 1: relu(+bias) -> g_rep(<300) + splits;
// MODE 2: -> aff hi;                        MODE 3: batched (z) -> out triplet.
template<int MODE>
__global__ __launch_bounds__(256, 3) void mma_gemm(
    const f16* __restrict__ Ahi, const f16* __restrict__ Alo, int lda, long aStride,
    const f16* __restrict__ Bhi, int ldb, long bStride,
    int M, int N, int nchunk,
    const float* __restrict__ bias, const int* __restrict__ postag,
    float* __restrict__ out)
{
    extern __shared__ char smem[];
    const uint32_t sbase = sm_u32(smem);
    const int tid = threadIdx.x;
    const int lane = tid & 31;
    const int warp = tid >> 5;
    const int warpM = warp >> 1;       // 0..3
    const int warpN = warp & 1;        // 0..1
    const int rowBase = blockIdx.y * 128;
    const int colBase = blockIdx.x * 64;
    const int z = blockIdx.z;

    const f16* ahi = Ahi + (long)z * aStride;
    const f16* alo = Alo + (long)z * aStride;
    const f16* bhi = Bhi + (long)z * bStride;

    // loader mapping
    const int lrow = tid >> 2;         // 0..63
    const int lc8  = tid & 3;          // 16B chunk within 64B row

    // ldmatrix per-lane offsets
    const int a_row = (lane & 7) + ((lane >> 3) & 1) * 8;
    const int a_kh  = lane >> 4;
    const uint32_t aoff = (uint32_t)((warpM * 32 + a_row) * 80 + a_kh * 16);
    const int b_n  = (lane & 7) + (lane >> 4) * 8;
    const int b_kh = (lane >> 3) & 1;
    const uint32_t boff = (uint32_t)((warpN * 32 + b_n) * 80 + b_kh * 16);

    float acc[2][4][4];
    #pragma unroll
    for (int m = 0; m < 2; m++)
        #pragma unroll
        for (int t = 0; t < 4; t++)
            #pragma unroll
            for (int r = 0; r < 4; r++) acc[m][t][r] = 0.f;

    // ---- async copy of one K-chunk (32 f16) into stage buffer ----
    auto issue = [&](int c) {
        const uint32_t bufb = sbase + (c % NSTAGE) * S_STAGE;
        const int kof = c * 32 + lc8 * 8;
        #pragma unroll
        for (int t = 0; t < 2; t++) {
            int row = lrow + t * 64;
            long gr = rowBase + row; if (gr > M - 1) gr = M - 1;
            uint32_t d = bufb + row * 80 + lc8 * 16;
            CP16(d + S_AH, ahi + gr * (long)lda + kof);
            CP16(d + S_AL, alo + gr * (long)lda + kof);
        }
        {
            long gn = colBase + lrow; if (gn > N - 1) gn = N - 1;
            uint32_t d = bufb + S_BH + lrow * 80 + lc8 * 16;
            CP16(d, bhi + gn * (long)ldb + kof);
        }
        CP_COMMIT();
    };

    issue(0);
    if (nchunk > 1) issue(1);

    for (int c = 0; c < nchunk; c++) {
        // group c must have landed; group c+1 may still be in flight
        if (c + 1 < nchunk) CP_WAIT1(); else CP_WAIT0();
        __syncthreads();            // everyone done reading buffer (c+2)%3 at iter c-1
        if (c + 2 < nchunk) issue(c + 2);

        const uint32_t bb = sbase + (c % NSTAGE) * S_STAGE;
        #pragma unroll
        for (int k16 = 0; k16 < 2; k16++) {
            const uint32_t ka = bb + k16 * 32 + aoff;
            const uint32_t kb = bb + k16 * 32 + boff;
            uint32_t ah[8], al[8], bh[8];
            LDSM4(ah[0], ah[1], ah[2], ah[3], ka + S_AH);
            LDSM4(ah[4], ah[5], ah[6], ah[7], ka + S_AH + 16 * 80);
            LDSM4(al[0], al[1], al[2], al[3], ka + S_AL);
            LDSM4(al[4], al[5], al[6], al[7], ka + S_AL + 16 * 80);
            LDSM4(bh[0], bh[1], bh[2], bh[3], kb + S_BH);
            LDSM4(bh[4], bh[5], bh[6], bh[7], kb + S_BH + 16 * 80);
            #pragma unroll
            for (int m = 0; m < 2; m++) {
                #pragma unroll
                for (int t8 = 0; t8 < 4; t8++) {
                    int g = t8 >> 1, s = t8 & 1;
                    uint32_t b0 = bh[g * 4 + s * 2], b1 = bh[g * 4 + s * 2 + 1];
                    MMA16816(acc[m][t8], ah[m*4], ah[m*4+1], ah[m*4+2], ah[m*4+3], b0, b1);
                    MMA16816(acc[m][t8], al[m*4], al[m*4+1], al[m*4+2], al[m*4+3], b0, b1);
                }
            }
        }
    }

    // ---- epilogue ----
    const int lr = lane >> 2;
    const int lc = (lane & 3) * 2;
    #pragma unroll
    for (int m = 0; m < 2; m++) {
        #pragma unroll
        for (int t8 = 0; t8 < 4; t8++) {
            #pragma unroll
            for (int ri = 0; ri < 4; ri++) {
                int gm = rowBase + warpM * 32 + m * 16 + lr + ((ri & 2) ? 8 : 0);
                int gn = colBase + warpN * 32 + t8 * 8 + lc + (ri & 1);
                if (gm >= M || gn >= N) continue;
                float v = acc[m][t8][ri];
                if (MODE == 0) {
                    v += g_tagtab[(long)postag[gm] * RR + gn];
                    hsplit(v, &g_rdh[(long)gm * KR2 + gn], &g_rdl[(long)gm * KR2 + gn]);
                } else if (MODE == 1) {
                    v = fmaxf(v + bias[gn], 0.f);
                    if (gn < 300) g_rep[(long)gm * N4 + gn] = v;   // tag heads need only these
                    if (gn >= 300 && gn < 450)
                        hsplit(v, &g_i1h[(long)gm * KBI2 + gn - 300],
                                  &g_i1l[(long)gm * KBI2 + gn - 300]);
                    else if (gn >= 450)
                        hsplit(v, &g_onh[(long)gm * KBI2 + gn - 450],
                                  &g_onl[(long)gm * KBI2 + gn - 450]);
                } else if (MODE == 2) {
                    int p = gn / HH, h = gn - p * HH;
                    g_afh[((long)gm * 4 + p) * KBI2 + h] = __float2half(v);
                } else {
                    out[(long)OUT_TRI_OFF + ((long)z * LL + gm) * KTRI + gn] = v;
                }
            }
        }
    }
}

// ---------------- postag table: T[t][n] = b_reduc[n] + embed[t] . W_reduc[n][:50] ----
__global__ void tagtab_kernel(const float* __restrict__ embed,
                              const float* __restrict__ W_reduc,
                              const float* __restrict__ b_reduc) {
    int idx = blockIdx.x * blockDim.x + threadIdx.x;
    if (idx >= NVOC * RR) return;
    int t = idx / RR, n = idx - t * RR;
    float s = b_reduc[n];
    #pragma unroll 10
    for (int j = 0; j < PD; j++) s += embed[t * PD + j] * W_reduc[n * FF + j];
    g_tagtab[idx] = s;
}

// ---------------- pack weights into f16 hi ----------------
__global__ void pack_kernel(const float* __restrict__ W_ap, const float* __restrict__ b_ap,
                            const float* __restrict__ W_op, const float* __restrict__ b_op,
                            const float* __restrict__ W_ap2, const float* __restrict__ b_ap2,
                            const float* __restrict__ W_op2, const float* __restrict__ b_op2,
                            const float* __restrict__ W_reduc, const float* __restrict__ W_bi) {
    int idx = blockIdx.x * blockDim.x + threadIdx.x;
    const int T0 = RR * FP;
    const int T1 = T0 + N4 * KR2;
    const int T2 = T1 + N4 * KBI2;
    const int T3 = T2 + N4;
    if (idx < T0) {
        int n = idx / FP, k = idx - n * FP;
        g_Wrh[idx] = __float2half(W_reduc[n * FF + PD + k]);   // word-vec columns only
    } else if (idx < T1) {
        int i = idx - T0;
        int n = i / KR2, k = i - n * KR2;
        float v = 0.f;
        if (k < RR) {
            const float* src; int nn = n;
            if (n < HH)          { src = W_ap;  }
            else if (n < 2 * HH) { src = W_op;  nn = n - HH; }
            else if (n < 3 * HH) { src = W_ap2; nn = n - 2 * HH; }
            else                 { src = W_op2; nn = n - 3 * HH; }
            v = src[nn * RR + k];
        }
        g_Wch[i] = __float2half(v);
    } else if (idx < T2) {
        int i = idx - T1;
        int n = i / KBI2, k = i - n * KBI2;
        float v = (k < HH + 1) ? W_bi[n * (HH + 1) + k] : 0.f;
        g_Wbh[i] = __float2half(v);
    } else if (idx < T3) {
        int n = idx - T2;
        const float* src; int nn = n;
        if (n < HH)          { src = b_ap;  }
        else if (n < 2 * HH) { src = b_op;  nn = n - HH; }
        else if (n < 3 * HH) { src = b_ap2; nn = n - 2 * HH; }
        else                 { src = b_op2; nn = n - 3 * HH; }
        g_bcat[n] = src[nn];
    }
}

// set bias-1 column of in1
__global__ void init_kernel() {
    int w = blockIdx.x * blockDim.x + threadIdx.x;
    if (w < NW) {
        g_i1h[(long)w * KBI2 + HH] = __float2half(1.0f);
        g_i1l[(long)w * KBI2 + HH] = __float2half(0.0f);
    }
}

// ---------------- pool subwords (word_vecs only), 4 dims/thread ----------------
__global__ void pool_kernel(const float* __restrict__ bert,
                            const int* __restrict__ positions) {
    int idx = blockIdx.x * blockDim.x + threadIdx.x;
    if (idx >= NW * (FP / 4)) return;
    int w  = idx / (FP / 4);
    int d4 = (idx - w * (FP / 4)) * 4;
    int s0 = positions[2 * w];
    int s1 = positions[2 * w + 1];
    int b  = w / LL;
    const float* base = bert + ((long)b * SS) * DD + d4;
    float4 s = make_float4(0.f, 0.f, 0.f, 0.f);
    for (int t = s0; t <= s1; t++) {
        float4 v = *(const float4*)(base + (long)t * DD);
        s.x += v.x; s.y += v.y; s.z += v.z; s.w += v.w;
    }
    float inv = 1.0f / (float)(s1 - s0 + 1);
    long o = (long)w * FP + d4;
    f16 h0, l0, h1, l1, h2, l2, h3, l3;
    hsplit(s.x * inv, &h0, &l0);
    hsplit(s.y * inv, &h1, &l1);
    hsplit(s.z * inv, &h2, &l2);
    hsplit(s.w * inv, &h3, &l3);
    __half2* ph = (__half2*)(g_hh + o);
    __half2* pl = (__half2*)(g_hl + o);
    ph[0] = __halves2half2(h0, h1);
    ph[1] = __halves2half2(h2, h3);
    pl[0] = __halves2half2(l0, l1);
    pl[1] = __halves2half2(l2, l3);
}

// ---------------- tag heads (tiny) ----------------
__global__ void tag_kernel(const float* __restrict__ W_aptag, const float* __restrict__ b_aptag,
                           const float* __restrict__ W_optag, const float* __restrict__ b_optag,
                           float* __restrict__ out) {
    int idx = blockIdx.x * blockDim.x + threadIdx.x;
    if (idx >= NW * 10) return;
    int w = idx / 10, t = idx - w * 10;
    const float* rep;
    const float* wv;
    float acc;
    int off;
    if (t < NTAG) {
        rep = g_rep + (long)w * N4;
        wv  = W_aptag + t * HH;
        acc = b_aptag[t];
        off = OUT_AP_OFF + w * NTAG + t;
    } else {
        int tt = t - NTAG;
        rep = g_rep + (long)w * N4 + HH;
        wv  = W_optag + tt * HH;
        acc = b_optag[tt];
        off = OUT_OP_OFF + w * NTAG + tt;
    }
    #pragma unroll 5
    for (int k = 0; k < HH; k++) acc += rep[k] * wv[k];
    out[off] = acc;
}

// ---------------- launch ----------------
extern "C" void kernel_launch(void* const* d_in, const int* in_sizes, int n_in,
                              void* d_out, int out_size) {
    const float* bert      = (const float*)d_in[0];
    const int*   positions = (const int*)  d_in[1];
    const int*   postag    = (const int*)  d_in[2];
    const float* embed     = (const float*)d_in[3];
    const float* W_reduc   = (const float*)d_in[4];
    const float* b_reduc   = (const float*)d_in[5];
    const float* W_ap      = (const float*)d_in[6];
    const float* b_ap      = (const float*)d_in[7];
    const float* W_op      = (const float*)d_in[8];
    const float* b_op      = (const float*)d_in[9];
    const float* W_ap2     = (const float*)d_in[10];
    const float* b_ap2     = (const float*)d_in[11];
    const float* W_op2     = (const float*)d_in[12];
    const float* b_op2     = (const float*)d_in[13];
    const float* W_aptag   = (const float*)d_in[14];
    const float* b_aptag   = (const float*)d_in[15];
    const float* W_optag   = (const float*)d_in[16];
    const float* b_optag   = (const float*)d_in[17];
    const float* W_bi      = (const float*)d_in[18];
    float* out = (float*)d_out;

    void* p;
    cudaGetSymbolAddress(&p, g_hh);   f16* phh  = (f16*)p;
    cudaGetSymbolAddress(&p, g_hl);   f16* phl  = (f16*)p;
    cudaGetSymbolAddress(&p, g_rdh);  f16* prdh = (f16*)p;
    cudaGetSymbolAddress(&p, g_rdl);  f16* prdl = (f16*)p;
    cudaGetSymbolAddress(&p, g_i1h);  f16* pi1h = (f16*)p;
    cudaGetSymbolAddress(&p, g_i1l);  f16* pi1l = (f16*)p;
    cudaGetSymbolAddress(&p, g_onh);  f16* ponh = (f16*)p;
    cudaGetSymbolAddress(&p, g_onl);  f16* ponl = (f16*)p;
    cudaGetSymbolAddress(&p, g_afh);  f16* pafh = (f16*)p;
    cudaGetSymbolAddress(&p, g_Wrh);  f16* pWrh = (f16*)p;
    cudaGetSymbolAddress(&p, g_Wch);  f16* pWch = (f16*)p;
    cudaGetSymbolAddress(&p, g_Wbh);  f16* pWbh = (f16*)p;
    cudaGetSymbolAddress(&p, g_bcat); float* pbcat = (float*)p;

    cudaFuncSetAttribute(mma_gemm<0>, cudaFuncAttributeMaxDynamicSharedMemorySize, SMEM_SZ);
    cudaFuncSetAttribute(mma_gemm<1>, cudaFuncAttributeMaxDynamicSharedMemorySize, SMEM_SZ);
    cudaFuncSetAttribute(mma_gemm<2>, cudaFuncAttributeMaxDynamicSharedMemorySize, SMEM_SZ);
    cudaFuncSetAttribute(mma_gemm<3>, cudaFuncAttributeMaxDynamicSharedMemorySize, SMEM_SZ);

    // 1) pack weights + tag table + bias column
    {
        int tot = RR * FP + N4 * KR2 + N4 * KBI2 + N4;
        pack_kernel<<<(tot + 255) / 256, 256>>>(W_ap, b_ap, W_op, b_op, W_ap2, b_ap2,
                                                W_op2, b_op2, W_reduc, W_bi);
        tagtab_kernel<<<(NVOC * RR + 255) / 256, 256>>>(embed, W_reduc, b_reduc);
        init_kernel<<<(NW + 255) / 256, 256>>>();
    }
    // 2) pool word_vecs -> f16 hi/lo (vectorized)
    {
        int tot = NW * (FP / 4);
        pool_kernel<<<(tot + 255) / 256, 256>>>(bert, positions);
    }
    // 3) gemm1: reduc = wv @ Wr^T + tagtab[postag]   M=25600, N=400, K=768 (24 chunks)
    {
        dim3 grid(7, NW / 128, 1);
        mma_gemm<0><<<grid, 256, SMEM_SZ>>>(phh, phl, FP, 0, pWrh, FP, 0,
                                            NW, RR, FP / 32, nullptr, postag, nullptr);
    }
    // 4) gemm2: rep = relu(reduc @ Wcat^T + bcat)  M=25600, N=600, K=416 (13 chunks)
    {
        dim3 grid(10, NW / 128, 1);
        mma_gemm<1><<<grid, 256, SMEM_SZ>>>(prdh, prdl, KR2, 0, pWch, KR2, 0,
                                            NW, N4, KR2 / 32, pbcat, nullptr, nullptr);
    }
    // 5) tag heads
    {
        int tot = NW * 10;
        tag_kernel<<<(tot + 255) / 256, 256>>>(W_aptag, b_aptag, W_optag, b_optag, out);
    }
    // 6) affine = in1 @ Wbi^T   M=25600, N=600, K=160 (5 chunks)
    {
        dim3 grid(10, NW / 128, 1);
        mma_gemm<2><<<grid, 256, SMEM_SZ>>>(pi1h, pi1l, KBI2, 0, pWbh, KBI2, 0,
                                            NW, N4, KBI2 / 32, nullptr, nullptr, nullptr);
    }
    // 7) tri: batched  M=200, N=800, K=160 per batch (5 chunks)
    {
        dim3 grid(13, 2, BB);
        mma_gemm<3><<<grid, 256, SMEM_SZ>>>(ponh, ponl, KBI2, (long)LL * KBI2,
                                            pafh, KBI2, (long)LL * 4 * KBI2,
                                            LL, KTRI, KBI2 / 32, nullptr, nullptr, out);
    }
}

// round 16
// speedup vs baseline: 2.0645x; 1.3560x over previous
#include <cuda_runtime.h>
#include <cuda_fp16.h>
#include <cstdint>

// ---------------- problem constants ----------------
#define BB   128
#define SS   256
#define LL   200
#define DD   768
#define PD   50
#define FF   818
#define FP   768             // gemm1 K = word_vec dims only (pos-emb folded into table)
#define RR   400
#define KR2  416             // gemm2 K padded
#define HH   150
#define NW   (BB * LL)       // 25600
#define NTAG 5
#define N4   600
#define KBI2 160             // affine/tri K padded (151 -> 160)
#define KTRI 800
#define NVOC 60
#define OUT_AP_OFF  0
#define OUT_OP_OFF  (NW * NTAG)
#define OUT_TRI_OFF (2 * NW * NTAG)

typedef __half f16;

// ---------------- scratch (__device__ globals, zero-init) ----------------
__device__ f16   g_hh[NW * FP];       // word_vecs (A of gemm1)
__device__ f16   g_rdh[NW * KR2];     // reduc (A of gemm2)
__device__ float g_rep[NW * N4];      // only cols 0..299 written/used
__device__ f16   g_i1h[NW * KBI2];    // [ap_node,1,0..] (A of affine)
__device__ f16   g_onh[NW * KBI2];    // [op_node,0..]   (A of tri)
__device__ f16   g_afh[NW * 4 * KBI2];// affine (B of tri)
__device__ f16   g_Wrh[RR * FP];      // B of gemm1 (word-vec cols)
__device__ f16   g_Wch[N4 * KR2];     // B of gemm2
__device__ f16   g_Wbh[N4 * KBI2];    // B of affine
__device__ float g_bcat[N4];
__device__ float g_tagtab[NVOC * RR]; // embed @ Wreduc[:, :50]^T + b_reduc

// ---------------- PTX helpers (baseline sm_80+ features only) ----------------
__device__ __forceinline__ uint32_t sm_u32(const void* p) {
    uint32_t a;
    asm("{ .reg .u64 t; cvta.to.shared.u64 t, %1; cvt.u32.u64 %0, t; }" : "=r"(a) : "l"(p));
    return a;
}

#define CP16(dst, src) \
    asm volatile("cp.async.cg.shared.global [%0], [%1], 16;" :: "r"(dst), "l"(src) : "memory")
#define CP_COMMIT() asm volatile("cp.async.commit_group;" ::: "memory")
#define CP_WAIT1()  asm volatile("cp.async.wait_group 1;" ::: "memory")
#define CP_WAIT0()  asm volatile("cp.async.wait_group 0;" ::: "memory")

#define LDSM4(r0, r1, r2, r3, addr) \
    asm volatile("ldmatrix.sync.aligned.m8n8.x4.shared.b16 {%0,%1,%2,%3}, [%4];" \
                 : "=r"(r0), "=r"(r1), "=r"(r2), "=r"(r3) : "r"(addr))

#define MMA16816(d, a0, a1, a2, a3, b0, b1) \
    asm volatile("mma.sync.aligned.m16n8k16.row.col.f32.f16.f16.f32 " \
                 "{%0,%1,%2,%3}, {%4,%5,%6,%7}, {%8,%9}, {%0,%1,%2,%3};" \
                 : "+f"((d)[0]), "+f"((d)[1]), "+f"((d)[2]), "+f"((d)[3]) \
                 : "r"(a0), "r"(a1), "r"(a2), "r"(a3), "r"(b0), "r"(b1))

// smem stage layout (bytes): rows of 32 f16 = 64B + 16B pad -> 80B row stride
// A 128x32, B 64x32
#define S_AH    0
#define S_BH    10240
#define S_STAGE 15360
#define NSTAGE  3
#define SMEM_SZ (NSTAGE * S_STAGE)    // 46080 -> 3 CTAs/SM comfortably

// ---------------- HMMA GEMM (plain fp16): C[M,N] = A[M,K] * B[N,K]^T ----
// 128x64 block tile, 8 warps (4Mx2N), warp tile 32x32, BK=32.
// 3-stage cp.async pipeline with wait_group 1.
// MODE 0: +tagtab[postag] -> reduc;  MODE 1: relu(+bias) -> g_rep(<300) + i1/on;
// MODE 2: -> aff;                     MODE 3: batched (z) -> out triplet.
template<int MODE>
__global__ __launch_bounds__(256, 3) void mma_gemm(
    const f16* __restrict__ A, int lda, long aStride,
    const f16* __restrict__ B, int ldb, long bStride,
    int M, int N, int nchunk,
    const float* __restrict__ bias, const int* __restrict__ postag,
    float* __restrict__ out)
{
    extern __shared__ char smem[];
    const uint32_t sbase = sm_u32(smem);
    const int tid = threadIdx.x;
    const int lane = tid & 31;
    const int warp = tid >> 5;
    const int warpM = warp >> 1;       // 0..3
    const int warpN = warp & 1;        // 0..1
    const int rowBase = blockIdx.y * 128;
    const int colBase = blockIdx.x * 64;
    const int z = blockIdx.z;

    const f16* ap = A + (long)z * aStride;
    const f16* bp = B + (long)z * bStride;

    // loader mapping
    const int lrow = tid >> 2;         // 0..63
    const int lc8  = tid & 3;          // 16B chunk within 64B row

    // ldmatrix per-lane offsets
    const int a_row = (lane & 7) + ((lane >> 3) & 1) * 8;
    const int a_kh  = lane >> 4;
    const uint32_t aoff = (uint32_t)((warpM * 32 + a_row) * 80 + a_kh * 16);
    const int b_n  = (lane & 7) + (lane >> 4) * 8;
    const int b_kh = (lane >> 3) & 1;
    const uint32_t boff = (uint32_t)((warpN * 32 + b_n) * 80 + b_kh * 16);

    float acc[2][4][4];
    #pragma unroll
    for (int m = 0; m < 2; m++)
        #pragma unroll
        for (int t = 0; t < 4; t++)
            #pragma unroll
            for (int r = 0; r < 4; r++) acc[m][t][r] = 0.f;

    // ---- async copy of one K-chunk (32 f16) into stage buffer ----
    auto issue = [&](int c) {
        const uint32_t bufb = sbase + (c % NSTAGE) * S_STAGE;
        const int kof = c * 32 + lc8 * 8;
        #pragma unroll
        for (int t = 0; t < 2; t++) {
            int row = lrow + t * 64;
            long gr = rowBase + row; if (gr > M - 1) gr = M - 1;
            CP16(bufb + row * 80 + lc8 * 16 + S_AH, ap + gr * (long)lda + kof);
        }
        {
            long gn = colBase + lrow; if (gn > N - 1) gn = N - 1;
            CP16(bufb + S_BH + lrow * 80 + lc8 * 16, bp + gn * (long)ldb + kof);
        }
        CP_COMMIT();
    };

    issue(0);
    if (nchunk > 1) issue(1);

    for (int c = 0; c < nchunk; c++) {
        if (c + 1 < nchunk) CP_WAIT1(); else CP_WAIT0();
        __syncthreads();
        if (c + 2 < nchunk) issue(c + 2);

        const uint32_t bb = sbase + (c % NSTAGE) * S_STAGE;
        #pragma unroll
        for (int k16 = 0; k16 < 2; k16++) {
            const uint32_t ka = bb + k16 * 32 + aoff;
            const uint32_t kb = bb + k16 * 32 + boff;
            uint32_t ah[8], bh[8];
            LDSM4(ah[0], ah[1], ah[2], ah[3], ka + S_AH);
            LDSM4(ah[4], ah[5], ah[6], ah[7], ka + S_AH + 16 * 80);
            LDSM4(bh[0], bh[1], bh[2], bh[3], kb + S_BH);
            LDSM4(bh[4], bh[5], bh[6], bh[7], kb + S_BH + 16 * 80);
            #pragma unroll
            for (int m = 0; m < 2; m++) {
                #pragma unroll
                for (int t8 = 0; t8 < 4; t8++) {
                    int g = t8 >> 1, s = t8 & 1;
                    MMA16816(acc[m][t8], ah[m*4], ah[m*4+1], ah[m*4+2], ah[m*4+3],
                             bh[g * 4 + s * 2], bh[g * 4 + s * 2 + 1]);
                }
            }
        }
    }

    // ---- epilogue ----
    const int lr = lane >> 2;
    const int lc = (lane & 3) * 2;
    #pragma unroll
    for (int m = 0; m < 2; m++) {
        #pragma unroll
        for (int t8 = 0; t8 < 4; t8++) {
            #pragma unroll
            for (int ri = 0; ri < 4; ri++) {
                int gm = rowBase + warpM * 32 + m * 16 + lr + ((ri & 2) ? 8 : 0);
                int gn = colBase + warpN * 32 + t8 * 8 + lc + (ri & 1);
                if (gm >= M || gn >= N) continue;
                float v = acc[m][t8][ri];
                if (MODE == 0) {
                    v += g_tagtab[(long)postag[gm] * RR + gn];
                    g_rdh[(long)gm * KR2 + gn] = __float2half(v);
                } else if (MODE == 1) {
                    v = fmaxf(v + bias[gn], 0.f);
                    if (gn < 300) g_rep[(long)gm * N4 + gn] = v;
                    if (gn >= 300 && gn < 450)
                        g_i1h[(long)gm * KBI2 + gn - 300] = __float2half(v);
                    else if (gn >= 450)
                        g_onh[(long)gm * KBI2 + gn - 450] = __float2half(v);
                } else if (MODE == 2) {
                    int p = gn / HH, h = gn - p * HH;
                    g_afh[((long)gm * 4 + p) * KBI2 + h] = __float2half(v);
                } else {
                    out[(long)OUT_TRI_OFF + ((long)z * LL + gm) * KTRI + gn] = v;
                }
            }
        }
    }
}

// ---------------- postag table: T[t][n] = b_reduc[n] + embed[t] . W_reduc[n][:50] ----
__global__ void tagtab_kernel(const float* __restrict__ embed,
                              const float* __restrict__ W_reduc,
                              const float* __restrict__ b_reduc) {
    int idx = blockIdx.x * blockDim.x + threadIdx.x;
    if (idx >= NVOC * RR) return;
    int t = idx / RR, n = idx - t * RR;
    float s = b_reduc[n];
    #pragma unroll 10
    for (int j = 0; j < PD; j++) s += embed[t * PD + j] * W_reduc[n * FF + j];
    g_tagtab[idx] = s;
}

// ---------------- pack weights into f16 ----------------
__global__ void pack_kernel(const float* __restrict__ W_ap, const float* __restrict__ b_ap,
                            const float* __restrict__ W_op, const float* __restrict__ b_op,
                            const float* __restrict__ W_ap2, const float* __restrict__ b_ap2,
                            const float* __restrict__ W_op2, const float* __restrict__ b_op2,
                            const float* __restrict__ W_reduc, const float* __restrict__ W_bi) {
    int idx = blockIdx.x * blockDim.x + threadIdx.x;
    const int T0 = RR * FP;
    const int T1 = T0 + N4 * KR2;
    const int T2 = T1 + N4 * KBI2;
    const int T3 = T2 + N4;
    if (idx < T0) {
        int n = idx / FP, k = idx - n * FP;
        g_Wrh[idx] = __float2half(W_reduc[n * FF + PD + k]);   // word-vec columns only
    } else if (idx < T1) {
        int i = idx - T0;
        int n = i / KR2, k = i - n * KR2;
        float v = 0.f;
        if (k < RR) {
            const float* src; int nn = n;
            if (n < HH)          { src = W_ap;  }
            else if (n < 2 * HH) { src = W_op;  nn = n - HH; }
            else if (n < 3 * HH) { src = W_ap2; nn = n - 2 * HH; }
            else                 { src = W_op2; nn = n - 3 * HH; }
            v = src[nn * RR + k];
        }
        g_Wch[i] = __float2half(v);
    } else if (idx < T2) {
        int i = idx - T1;
        int n = i / KBI2, k = i - n * KBI2;
        float v = (k < HH + 1) ? W_bi[n * (HH + 1) + k] : 0.f;
        g_Wbh[i] = __float2half(v);
    } else if (idx < T3) {
        int n = idx - T2;
        const float* src; int nn = n;
        if (n < HH)          { src = b_ap;  }
        else if (n < 2 * HH) { src = b_op;  nn = n - HH; }
        else if (n < 3 * HH) { src = b_ap2; nn = n - 2 * HH; }
        else                 { src = b_op2; nn = n - 3 * HH; }
        g_bcat[n] = src[nn];
    }
}

// set bias-1 column of in1
__global__ void init_kernel() {
    int w = blockIdx.x * blockDim.x + threadIdx.x;
    if (w < NW) g_i1h[(long)w * KBI2 + HH] = __float2half(1.0f);
}

// ---------------- pool subwords (word_vecs only), 4 dims/thread ----------------
__global__ void pool_kernel(const float* __restrict__ bert,
                            const int* __restrict__ positions) {
    int idx = blockIdx.x * blockDim.x + threadIdx.x;
    if (idx >= NW * (FP / 4)) return;
    int w  = idx / (FP / 4);
    int d4 = (idx - w * (FP / 4)) * 4;
    int s0 = positions[2 * w];
    int s1 = positions[2 * w + 1];
    int b  = w / LL;
    const float* base = bert + ((long)b * SS) * DD + d4;
    float4 s = make_float4(0.f, 0.f, 0.f, 0.f);
    for (int t = s0; t <= s1; t++) {
        float4 v = *(const float4*)(base + (long)t * DD);
        s.x += v.x; s.y += v.y; s.z += v.z; s.w += v.w;
    }
    float inv = 1.0f / (float)(s1 - s0 + 1);
    long o = (long)w * FP + d4;
    __half2* ph = (__half2*)(g_hh + o);
    ph[0] = __halves2half2(__float2half(s.x * inv), __float2half(s.y * inv));
    ph[1] = __halves2half2(__float2half(s.z * inv), __float2half(s.w * inv));
}

// ---------------- tag heads (tiny) ----------------
__global__ void tag_kernel(const float* __restrict__ W_aptag, const float* __restrict__ b_aptag,
                           const float* __restrict__ W_optag, const float* __restrict__ b_optag,
                           float* __restrict__ out) {
    int idx = blockIdx.x * blockDim.x + threadIdx.x;
    if (idx >= NW * 10) return;
    int w = idx / 10, t = idx - w * 10;
    const float* rep;
    const float* wv;
    float acc;
    int off;
    if (t < NTAG) {
        rep = g_rep + (long)w * N4;
        wv  = W_aptag + t * HH;
        acc = b_aptag[t];
        off = OUT_AP_OFF + w * NTAG + t;
    } else {
        int tt = t - NTAG;
        rep = g_rep + (long)w * N4 + HH;
        wv  = W_optag + tt * HH;
        acc = b_optag[tt];
        off = OUT_OP_OFF + w * NTAG + tt;
    }
    #pragma unroll 5
    for (int k = 0; k < HH; k++) acc += rep[k] * wv[k];
    out[off] = acc;
}

// ---------------- launch ----------------
extern "C" void kernel_launch(void* const* d_in, const int* in_sizes, int n_in,
                              void* d_out, int out_size) {
    const float* bert      = (const float*)d_in[0];
    const int*   positions = (const int*)  d_in[1];
    const int*   postag    = (const int*)  d_in[2];
    const float* embed     = (const float*)d_in[3];
    const float* W_reduc   = (const float*)d_in[4];
    const float* b_reduc   = (const float*)d_in[5];
    const float* W_ap      = (const float*)d_in[6];
    const float* b_ap      = (const float*)d_in[7];
    const float* W_op      = (const float*)d_in[8];
    const float* b_op      = (const float*)d_in[9];
    const float* W_ap2     = (const float*)d_in[10];
    const float* b_ap2     = (const float*)d_in[11];
    const float* W_op2     = (const float*)d_in[12];
    const float* b_op2     = (const float*)d_in[13];
    const float* W_aptag   = (const float*)d_in[14];
    const float* b_aptag   = (const float*)d_in[15];
    const float* W_optag   = (const float*)d_in[16];
    const float* b_optag   = (const float*)d_in[17];
    const float* W_bi      = (const float*)d_in[18];
    float* out = (float*)d_out;

    void* p;
    cudaGetSymbolAddress(&p, g_hh);   f16* phh  = (f16*)p;
    cudaGetSymbolAddress(&p, g_rdh);  f16* prdh = (f16*)p;
    cudaGetSymbolAddress(&p, g_i1h);  f16* pi1h = (f16*)p;
    cudaGetSymbolAddress(&p, g_onh);  f16* ponh = (f16*)p;
    cudaGetSymbolAddress(&p, g_afh);  f16* pafh = (f16*)p;
    cudaGetSymbolAddress(&p, g_Wrh);  f16* pWrh = (f16*)p;
    cudaGetSymbolAddress(&p, g_Wch);  f16* pWch = (f16*)p;
    cudaGetSymbolAddress(&p, g_Wbh);  f16* pWbh = (f16*)p;
    cudaGetSymbolAddress(&p, g_bcat); float* pbcat = (float*)p;

    cudaFuncSetAttribute(mma_gemm<0>, cudaFuncAttributeMaxDynamicSharedMemorySize, SMEM_SZ);
    cudaFuncSetAttribute(mma_gemm<1>, cudaFuncAttributeMaxDynamicSharedMemorySize, SMEM_SZ);
    cudaFuncSetAttribute(mma_gemm<2>, cudaFuncAttributeMaxDynamicSharedMemorySize, SMEM_SZ);
    cudaFuncSetAttribute(mma_gemm<3>, cudaFuncAttributeMaxDynamicSharedMemorySize, SMEM_SZ);

    // 1) pack weights + tag table + bias column
    {
        int tot = RR * FP + N4 * KR2 + N4 * KBI2 + N4;
        pack_kernel<<<(tot + 255) / 256, 256>>>(W_ap, b_ap, W_op, b_op, W_ap2, b_ap2,
                                                W_op2, b_op2, W_reduc, W_bi);
        tagtab_kernel<<<(NVOC * RR + 255) / 256, 256>>>(embed, W_reduc, b_reduc);
        init_kernel<<<(NW + 255) / 256, 256>>>();
    }
    // 2) pool word_vecs -> f16 (vectorized)
    {
        int tot = NW * (FP / 4);
        pool_kernel<<<(tot + 255) / 256, 256>>>(bert, positions);
    }
    // 3) gemm1: reduc = wv @ Wr^T + tagtab[postag]   M=25600, N=400, K=768 (24 chunks)
    {
        dim3 grid(7, NW / 128, 1);
        mma_gemm<0><<<grid, 256, SMEM_SZ>>>(phh, FP, 0, pWrh, FP, 0,
                                            NW, RR, FP / 32, nullptr, postag, nullptr);
    }
    // 4) gemm2: rep = relu(reduc @ Wcat^T + bcat)  M=25600, N=600, K=416 (13 chunks)
    {
        dim3 grid(10, NW / 128, 1);
        mma_gemm<1><<<grid, 256, SMEM_SZ>>>(prdh, KR2, 0, pWch, KR2, 0,
                                            NW, N4, KR2 / 32, pbcat, nullptr, nullptr);
    }
    // 5) tag heads
    {
        int tot = NW * 10;
        tag_kernel<<<(tot + 255) / 256, 256>>>(W_aptag, b_aptag, W_optag, b_optag, out);
    }
    // 6) affine = in1 @ Wbi^T   M=25600, N=600, K=160 (5 chunks)
    {
        dim3 grid(10, NW / 128, 1);
        mma_gemm<2><<<grid, 256, SMEM_SZ>>>(pi1h, KBI2, 0, pWbh, KBI2, 0,
                                            NW, N4, KBI2 / 32, nullptr, nullptr, nullptr);
    }
    // 7) tri: batched  M=200, N=800, K=160 per batch (5 chunks)
    {
        dim3 grid(13, 2, BB);
        mma_gemm<3><<<grid, 256, SMEM_SZ>>>(ponh, KBI2, (long)LL * KBI2,
                                            pafh, KBI2, (long)LL * 4 * KBI2,
                                            LL, KTRI, KBI2 / 32, nullptr, nullptr, out);
    }
}

// round 17
// speedup vs baseline: 2.2481x; 1.0889x over previous
#include <cuda_runtime.h>
#include <cuda_fp16.h>
#include <cstdint>

// ---------------- problem constants ----------------
#define BB   128
#define SS   256
#define LL   200
#define DD   768
#define PD   50
#define FF   818
#define FP   768             // gemm1 K = word_vec dims only (pos-emb folded into table)
#define RR   400
#define KR2  416             // gemm2 K padded
#define HH   150
#define NW   (BB * LL)       // 25600
#define NTAG 5
#define N4   600
#define KBI2 160             // affine/tri K padded (151 -> 160)
#define KTRI 800
#define NVOC 60
#define OUT_AP_OFF  0
#define OUT_OP_OFF  (NW * NTAG)
#define OUT_TRI_OFF (2 * NW * NTAG)

typedef __half f16;

// ---------------- scratch (__device__ globals, zero-init) ----------------
__device__ f16   g_hh[NW * FP];       // word_vecs (A of gemm1)
__device__ f16   g_rdh[NW * KR2];     // reduc (A of gemm2)
__device__ float g_rep[NW * N4];      // only cols 0..299 written/used
__device__ f16   g_i1h[NW * KBI2];    // [ap_node,1,0..] (A of affine)
__device__ f16   g_onh[NW * KBI2];    // [op_node,0..]   (A of tri)
__device__ f16   g_afh[NW * 4 * KBI2];// affine (B of tri)
__device__ f16   g_Wrh[RR * FP];      // B of gemm1 (word-vec cols)
__device__ f16   g_Wch[N4 * KR2];     // B of gemm2
__device__ f16   g_Wbh[N4 * KBI2];    // B of affine
__device__ float g_bcat[N4];
__device__ float g_tagtab[NVOC * RR]; // embed @ Wreduc[:, :50]^T + b_reduc

// ---------------- PTX helpers (baseline sm_80+ features only) ----------------
__device__ __forceinline__ uint32_t sm_u32(const void* p) {
    uint32_t a;
    asm("{ .reg .u64 t; cvta.to.shared.u64 t, %1; cvt.u32.u64 %0, t; }" : "=r"(a) : "l"(p));
    return a;
}

#define CP16(dst, src) \
    asm volatile("cp.async.cg.shared.global [%0], [%1], 16;" :: "r"(dst), "l"(src) : "memory")
#define CP_COMMIT() asm volatile("cp.async.commit_group;" ::: "memory")
#define CP_WAIT1()  asm volatile("cp.async.wait_group 1;" ::: "memory")
#define CP_WAIT0()  asm volatile("cp.async.wait_group 0;" ::: "memory")

#define LDSM4(r0, r1, r2, r3, addr) \
    asm volatile("ldmatrix.sync.aligned.m8n8.x4.shared.b16 {%0,%1,%2,%3}, [%4];" \
                 : "=r"(r0), "=r"(r1), "=r"(r2), "=r"(r3) : "r"(addr))

#define MMA16816(d, a0, a1, a2, a3, b0, b1) \
    asm volatile("mma.sync.aligned.m16n8k16.row.col.f32.f16.f16.f32 " \
                 "{%0,%1,%2,%3}, {%4,%5,%6,%7}, {%8,%9}, {%0,%1,%2,%3};" \
                 : "+f"((d)[0]), "+f"((d)[1]), "+f"((d)[2]), "+f"((d)[3]) \
                 : "r"(a0), "r"(a1), "r"(a2), "r"(a3), "r"(b0), "r"(b1))

// smem stage layout (bytes): rows of 32 f16 = 64B + 16B pad -> 80B row stride
// A 128x32, B 64x32
#define S_AH    0
#define S_BH    10240
#define S_STAGE 15360
#define NSTAGE  3
#define SMEM_SZ (NSTAGE * S_STAGE)    // 46080 -> 3 CTAs/SM comfortably

// ---------------- HMMA GEMM (plain fp16): C[M,N] = A[M,K] * B[N,K]^T ----
// 128x64 block tile, 8 warps (4Mx2N), warp tile 32x32, BK=32.
// 3-stage cp.async pipeline with wait_group 1.
// MODE 0: +tagtab[postag] -> reduc;  MODE 1: relu(+bias) -> g_rep(<300) + i1/on;
// MODE 2: -> aff;                     MODE 3: batched (z) -> out triplet.
template<int MODE>
__global__ __launch_bounds__(256, 3) void mma_gemm(
    const f16* __restrict__ A, int lda, long aStride,
    const f16* __restrict__ B, int ldb, long bStride,
    int M, int N, int nchunk,
    const float* __restrict__ bias, const int* __restrict__ postag,
    float* __restrict__ out)
{
    extern __shared__ char smem[];
    const uint32_t sbase = sm_u32(smem);
    const int tid = threadIdx.x;
    const int lane = tid & 31;
    const int warp = tid >> 5;
    const int warpM = warp >> 1;       // 0..3
    const int warpN = warp & 1;        // 0..1
    const int rowBase = blockIdx.y * 128;
    const int colBase = blockIdx.x * 64;
    const int z = blockIdx.z;

    const f16* ap = A + (long)z * aStride;
    const f16* bp = B + (long)z * bStride;

    // loader mapping
    const int lrow = tid >> 2;         // 0..63
    const int lc8  = tid & 3;          // 16B chunk within 64B row

    // ldmatrix per-lane offsets
    const int a_row = (lane & 7) + ((lane >> 3) & 1) * 8;
    const int a_kh  = lane >> 4;
    const uint32_t aoff = (uint32_t)((warpM * 32 + a_row) * 80 + a_kh * 16);
    const int b_n  = (lane & 7) + (lane >> 4) * 8;
    const int b_kh = (lane >> 3) & 1;
    const uint32_t boff = (uint32_t)((warpN * 32 + b_n) * 80 + b_kh * 16);

    float acc[2][4][4];
    #pragma unroll
    for (int m = 0; m < 2; m++)
        #pragma unroll
        for (int t = 0; t < 4; t++)
            #pragma unroll
            for (int r = 0; r < 4; r++) acc[m][t][r] = 0.f;

    // ---- async copy of one K-chunk (32 f16) into stage buffer ----
    auto issue = [&](int c) {
        const uint32_t bufb = sbase + (c % NSTAGE) * S_STAGE;
        const int kof = c * 32 + lc8 * 8;
        #pragma unroll
        for (int t = 0; t < 2; t++) {
            int row = lrow + t * 64;
            long gr = rowBase + row; if (gr > M - 1) gr = M - 1;
            CP16(bufb + row * 80 + lc8 * 16 + S_AH, ap + gr * (long)lda + kof);
        }
        {
            long gn = colBase + lrow; if (gn > N - 1) gn = N - 1;
            CP16(bufb + S_BH + lrow * 80 + lc8 * 16, bp + gn * (long)ldb + kof);
        }
        CP_COMMIT();
    };

    issue(0);
    if (nchunk > 1) issue(1);

    for (int c = 0; c < nchunk; c++) {
        if (c + 1 < nchunk) CP_WAIT1(); else CP_WAIT0();
        __syncthreads();
        if (c + 2 < nchunk) issue(c + 2);

        const uint32_t bb = sbase + (c % NSTAGE) * S_STAGE;
        #pragma unroll
        for (int k16 = 0; k16 < 2; k16++) {
            const uint32_t ka = bb + k16 * 32 + aoff;
            const uint32_t kb = bb + k16 * 32 + boff;
            uint32_t ah[8], bh[8];
            LDSM4(ah[0], ah[1], ah[2], ah[3], ka + S_AH);
            LDSM4(ah[4], ah[5], ah[6], ah[7], ka + S_AH + 16 * 80);
            LDSM4(bh[0], bh[1], bh[2], bh[3], kb + S_BH);
            LDSM4(bh[4], bh[5], bh[6], bh[7], kb + S_BH + 16 * 80);
            #pragma unroll
            for (int m = 0; m < 2; m++) {
                #pragma unroll
                for (int t8 = 0; t8 < 4; t8++) {
                    int g = t8 >> 1, s = t8 & 1;
                    MMA16816(acc[m][t8], ah[m*4], ah[m*4+1], ah[m*4+2], ah[m*4+3],
                             bh[g * 4 + s * 2], bh[g * 4 + s * 2 + 1]);
                }
            }
        }
    }

    // ---- epilogue ----
    const int lr = lane >> 2;
    const int lc = (lane & 3) * 2;
    #pragma unroll
    for (int m = 0; m < 2; m++) {
        #pragma unroll
        for (int t8 = 0; t8 < 4; t8++) {
            #pragma unroll
            for (int ri = 0; ri < 4; ri++) {
                int gm = rowBase + warpM * 32 + m * 16 + lr + ((ri & 2) ? 8 : 0);
                int gn = colBase + warpN * 32 + t8 * 8 + lc + (ri & 1);
                if (gm >= M || gn >= N) continue;
                float v = acc[m][t8][ri];
                if (MODE == 0) {
                    v += g_tagtab[(long)postag[gm] * RR + gn];
                    g_rdh[(long)gm * KR2 + gn] = __float2half(v);
                } else if (MODE == 1) {
                    v = fmaxf(v + bias[gn], 0.f);
                    if (gn < 300) g_rep[(long)gm * N4 + gn] = v;
                    if (gn >= 300 && gn < 450)
                        g_i1h[(long)gm * KBI2 + gn - 300] = __float2half(v);
                    else if (gn >= 450)
                        g_onh[(long)gm * KBI2 + gn - 450] = __float2half(v);
                } else if (MODE == 2) {
                    int p = gn / HH, h = gn - p * HH;
                    g_afh[((long)gm * 4 + p) * KBI2 + h] = __float2half(v);
                } else {
                    out[(long)OUT_TRI_OFF + ((long)z * LL + gm) * KTRI + gn] = v;
                }
            }
        }
    }
}

// ---------------- postag table: T[t][n] = b_reduc[n] + embed[t] . W_reduc[n][:50] ----
__global__ void tagtab_kernel(const float* __restrict__ embed,
                              const float* __restrict__ W_reduc,
                              const float* __restrict__ b_reduc) {
    int idx = blockIdx.x * blockDim.x + threadIdx.x;
    if (idx >= NVOC * RR) return;
    int t = idx / RR, n = idx - t * RR;
    float s = b_reduc[n];
    #pragma unroll 10
    for (int j = 0; j < PD; j++) s += embed[t * PD + j] * W_reduc[n * FF + j];
    g_tagtab[idx] = s;
}

// ---------------- pack weights into f16 ----------------
__global__ void pack_kernel(const float* __restrict__ W_ap, const float* __restrict__ b_ap,
                            const float* __restrict__ W_op, const float* __restrict__ b_op,
                            const float* __restrict__ W_ap2, const float* __restrict__ b_ap2,
                            const float* __restrict__ W_op2, const float* __restrict__ b_op2,
                            const float* __restrict__ W_reduc, const float* __restrict__ W_bi) {
    int idx = blockIdx.x * blockDim.x + threadIdx.x;
    const int T0 = RR * FP;
    const int T1 = T0 + N4 * KR2;
    const int T2 = T1 + N4 * KBI2;
    const int T3 = T2 + N4;
    if (idx < T0) {
        int n = idx / FP, k = idx - n * FP;
        g_Wrh[idx] = __float2half(W_reduc[n * FF + PD + k]);   // word-vec columns only
    } else if (idx < T1) {
        int i = idx - T0;
        int n = i / KR2, k = i - n * KR2;
        float v = 0.f;
        if (k < RR) {
            const float* src; int nn = n;
            if (n < HH)          { src = W_ap;  }
            else if (n < 2 * HH) { src = W_op;  nn = n - HH; }
            else if (n < 3 * HH) { src = W_ap2; nn = n - 2 * HH; }
            else                 { src = W_op2; nn = n - 3 * HH; }
            v = src[nn * RR + k];
        }
        g_Wch[i] = __float2half(v);
    } else if (idx < T2) {
        int i = idx - T1;
        int n = i / KBI2, k = i - n * KBI2;
        float v = (k < HH + 1) ? W_bi[n * (HH + 1) + k] : 0.f;
        g_Wbh[i] = __float2half(v);
    } else if (idx < T3) {
        int n = idx - T2;
        const float* src; int nn = n;
        if (n < HH)          { src = b_ap;  }
        else if (n < 2 * HH) { src = b_op;  nn = n - HH; }
        else if (n < 3 * HH) { src = b_ap2; nn = n - 2 * HH; }
        else                 { src = b_op2; nn = n - 3 * HH; }
        g_bcat[n] = src[nn];
    }
}

// set bias-1 column of in1
__global__ void init_kernel() {
    int w = blockIdx.x * blockDim.x + threadIdx.x;
    if (w < NW) g_i1h[(long)w * KBI2 + HH] = __float2half(1.0f);
}

// ---------------- pool subwords (word_vecs only), 8 dims/thread ----------------
__global__ void pool_kernel(const float* __restrict__ bert,
                            const int* __restrict__ positions) {
    int idx = blockIdx.x * blockDim.x + threadIdx.x;
    if (idx >= NW * (FP / 8)) return;
    int w  = idx / (FP / 8);
    int d8 = (idx - w * (FP / 8)) * 8;
    int s0 = positions[2 * w];
    int s1 = positions[2 * w + 1];
    int b  = w / LL;
    const float* base = bert + ((long)b * SS) * DD + d8;
    float4 sa = make_float4(0.f, 0.f, 0.f, 0.f);
    float4 sb = make_float4(0.f, 0.f, 0.f, 0.f);
    for (int t = s0; t <= s1; t++) {
        const float4* pv = (const float4*)(base + (long)t * DD);
        float4 v0 = pv[0];
        float4 v1 = pv[1];
        sa.x += v0.x; sa.y += v0.y; sa.z += v0.z; sa.w += v0.w;
        sb.x += v1.x; sb.y += v1.y; sb.z += v1.z; sb.w += v1.w;
    }
    float inv = 1.0f / (float)(s1 - s0 + 1);
    long o = (long)w * FP + d8;
    __half2* ph = (__half2*)(g_hh + o);
    ph[0] = __halves2half2(__float2half(sa.x * inv), __float2half(sa.y * inv));
    ph[1] = __halves2half2(__float2half(sa.z * inv), __float2half(sa.w * inv));
    ph[2] = __halves2half2(__float2half(sb.x * inv), __float2half(sb.y * inv));
    ph[3] = __halves2half2(__float2half(sb.z * inv), __float2half(sb.w * inv));
}

// ---------------- tag heads: warp per word, smem-staged weights ----------------
__global__ __launch_bounds__(256) void tag_kernel(
    const float* __restrict__ W_aptag, const float* __restrict__ b_aptag,
    const float* __restrict__ W_optag, const float* __restrict__ b_optag,
    float* __restrict__ out)
{
    __shared__ float sWa[NTAG * HH];   // 750
    __shared__ float sWo[NTAG * HH];   // 750
    __shared__ float sBa[NTAG], sBo[NTAG];
    const int tid = threadIdx.x;
    for (int i = tid; i < NTAG * HH; i += 256) {
        sWa[i] = W_aptag[i];
        sWo[i] = W_optag[i];
    }
    if (tid < NTAG)            sBa[tid] = b_aptag[tid];
    else if (tid < 2 * NTAG)   sBo[tid - NTAG] = b_optag[tid - NTAG];
    __syncthreads();

    const int lane = tid & 31;
    const int w = blockIdx.x * 8 + (tid >> 5);
    if (w >= NW) return;
    const float* rep = g_rep + (long)w * N4;

    float p[2 * NTAG];
    #pragma unroll
    for (int t = 0; t < 2 * NTAG; t++) p[t] = 0.f;

    #pragma unroll
    for (int k5 = 0; k5 < 5; k5++) {
        int k = k5 * 32 + lane;
        if (k < HH) {
            float a = rep[k];
            float o = rep[HH + k];
            #pragma unroll
            for (int t = 0; t < NTAG; t++) {
                p[t]        += a * sWa[t * HH + k];
                p[NTAG + t] += o * sWo[t * HH + k];
            }
        }
    }
    #pragma unroll
    for (int off = 16; off > 0; off >>= 1)
        #pragma unroll
        for (int t = 0; t < 2 * NTAG; t++)
            p[t] += __shfl_xor_sync(0xFFFFFFFFu, p[t], off);

    if (lane == 0) {
        #pragma unroll
        for (int t = 0; t < NTAG; t++) {
            out[OUT_AP_OFF + w * NTAG + t] = p[t] + sBa[t];
            out[OUT_OP_OFF + w * NTAG + t] = p[NTAG + t] + sBo[t];
        }
    }
}

// ---------------- launch ----------------
extern "C" void kernel_launch(void* const* d_in, const int* in_sizes, int n_in,
                              void* d_out, int out_size) {
    const float* bert      = (const float*)d_in[0];
    const int*   positions = (const int*)  d_in[1];
    const int*   postag    = (const int*)  d_in[2];
    const float* embed     = (const float*)d_in[3];
    const float* W_reduc   = (const float*)d_in[4];
    const float* b_reduc   = (const float*)d_in[5];
    const float* W_ap      = (const float*)d_in[6];
    const float* b_ap      = (const float*)d_in[7];
    const float* W_op      = (const float*)d_in[8];
    const float* b_op      = (const float*)d_in[9];
    const float* W_ap2     = (const float*)d_in[10];
    const float* b_ap2     = (const float*)d_in[11];
    const float* W_op2     = (const float*)d_in[12];
    const float* b_op2     = (const float*)d_in[13];
    const float* W_aptag   = (const float*)d_in[14];
    const float* b_aptag   = (const float*)d_in[15];
    const float* W_optag   = (const float*)d_in[16];
    const float* b_optag   = (const float*)d_in[17];
    const float* W_bi      = (const float*)d_in[18];
    float* out = (float*)d_out;

    void* p;
    cudaGetSymbolAddress(&p, g_hh);   f16* phh  = (f16*)p;
    cudaGetSymbolAddress(&p, g_rdh);  f16* prdh = (f16*)p;
    cudaGetSymbolAddress(&p, g_i1h);  f16* pi1h = (f16*)p;
    cudaGetSymbolAddress(&p, g_onh);  f16* ponh = (f16*)p;
    cudaGetSymbolAddress(&p, g_afh);  f16* pafh = (f16*)p;
    cudaGetSymbolAddress(&p, g_Wrh);  f16* pWrh = (f16*)p;
    cudaGetSymbolAddress(&p, g_Wch);  f16* pWch = (f16*)p;
    cudaGetSymbolAddress(&p, g_Wbh);  f16* pWbh = (f16*)p;
    cudaGetSymbolAddress(&p, g_bcat); float* pbcat = (float*)p;

    cudaFuncSetAttribute(mma_gemm<0>, cudaFuncAttributeMaxDynamicSharedMemorySize, SMEM_SZ);
    cudaFuncSetAttribute(mma_gemm<1>, cudaFuncAttributeMaxDynamicSharedMemorySize, SMEM_SZ);
    cudaFuncSetAttribute(mma_gemm<2>, cudaFuncAttributeMaxDynamicSharedMemorySize, SMEM_SZ);
    cudaFuncSetAttribute(mma_gemm<3>, cudaFuncAttributeMaxDynamicSharedMemorySize, SMEM_SZ);

    // 1) pack weights + tag table + bias column
    {
        int tot = RR * FP + N4 * KR2 + N4 * KBI2 + N4;
        pack_kernel<<<(tot + 255) / 256, 256>>>(W_ap, b_ap, W_op, b_op, W_ap2, b_ap2,
                                                W_op2, b_op2, W_reduc, W_bi);
        tagtab_kernel<<<(NVOC * RR + 255) / 256, 256>>>(embed, W_reduc, b_reduc);
        init_kernel<<<(NW + 255) / 256, 256>>>();
    }
    // 2) pool word_vecs -> f16 (8 dims/thread)
    {
        int tot = NW * (FP / 8);
        pool_kernel<<<(tot + 255) / 256, 256>>>(bert, positions);
    }
    // 3) gemm1: reduc = wv @ Wr^T + tagtab[postag]   M=25600, N=400, K=768 (24 chunks)
    {
        dim3 grid(7, NW / 128, 1);
        mma_gemm<0><<<grid, 256, SMEM_SZ>>>(phh, FP, 0, pWrh, FP, 0,
                                            NW, RR, FP / 32, nullptr, postag, nullptr);
    }
    // 4) gemm2: rep = relu(reduc @ Wcat^T + bcat)  M=25600, N=600, K=416 (13 chunks)
    {
        dim3 grid(10, NW / 128, 1);
        mma_gemm<1><<<grid, 256, SMEM_SZ>>>(prdh, KR2, 0, pWch, KR2, 0,
                                            NW, N4, KR2 / 32, pbcat, nullptr, nullptr);
    }
    // 5) tag heads (warp per word)
    {
        tag_kernel<<<NW / 8, 256>>>(W_aptag, b_aptag, W_optag, b_optag, out);
    }
    // 6) affine = in1 @ Wbi^T   M=25600, N=600, K=160 (5 chunks)
    {
        dim3 grid(10, NW / 128, 1);
        mma_gemm<2><<<grid, 256, SMEM_SZ>>>(pi1h, KBI2, 0, pWbh, KBI2, 0,
                                            NW, N4, KBI2 / 32, nullptr, nullptr, nullptr);
    }
    // 7) tri: batched  M=200, N=800, K=160 per batch (5 chunks)
    {
        dim3 grid(13, 2, BB);
        mma_gemm<3><<<grid, 256, SMEM_SZ>>>(ponh, KBI2, (long)LL * KBI2,
                                            pafh, KBI2, (long)LL * 4 * KBI2,
                                            LL, KTRI, KBI2 / 32, nullptr, nullptr, out);
    }
}